// round 1
// baseline (speedup 1.0000x reference)
#include <cuda_runtime.h>
#include <math.h>

#define SEQ   4096
#define DIM   2048
#define NH    16
#define QL    1536
#define KVL   512
#define NOPE  128
#define ROPE_D 64
#define QKH   192          // NOPE + ROPE
#define DCAT  576          // KVL + ROPE
#define SCALE_F 0.07216878364870322f  // 1/sqrt(192)

#define ATT_SMEM (2 * 32 * 580 * 4)   // sQ + sK, padded rows (580 = 576+4)

// ---------------- scratch (device globals; no allocations allowed) -------------
__device__ float g_qa[SEQ * QL];            // x @ wq_a^T, then rmsnorm in-place
__device__ float g_q[SEQ * NH * QKH];       // q_a_norm @ wq_b^T
__device__ float g_kva[SEQ * DCAT];         // x @ wkv_a^T
__device__ float g_kcat[SEQ * DCAT];        // [rmsnorm(kv_latent) | rope(k_pe)]
__device__ float g_qcat[NH * SEQ * DCAT];   // per-head [q_abs | rope(q_pe)]
__device__ float g_ctx[NH * SEQ * KVL];     // attention output (latent space)
__device__ float g_v[SEQ * DIM];            // per-head v projections, packed
__device__ float g_cos[SEQ * 32];
__device__ float g_sin[SEQ * 32];

// ---------------- generic tiled GEMM: C = A @ B^T (TN) or A @ B (NN) ----------
// Batched via blockIdx.z with element strides. Requires M%64==0, N%64==0, K%16==0.
template <bool TRANSB>
__global__ __launch_bounds__(256)
void gemm_k(const float* __restrict__ A, int lda, long long strA,
            const float* __restrict__ B, int ldb, long long strB,
            float* __restrict__ C, int ldc, long long strC,
            int M, int N, int K)
{
    __shared__ float sA[16][65];
    __shared__ float sB[16][65];
    A += (long long)blockIdx.z * strA;
    B += (long long)blockIdx.z * strB;
    C += (long long)blockIdx.z * strC;
    const int m0 = blockIdx.y * 64;
    const int n0 = blockIdx.x * 64;
    const int tid = threadIdx.x;
    const int tx = tid & 15;
    const int ty = tid >> 4;

    float acc[4][4];
#pragma unroll
    for (int i = 0; i < 4; i++)
#pragma unroll
        for (int j = 0; j < 4; j++) acc[i][j] = 0.f;

    for (int k0 = 0; k0 < K; k0 += 16) {
#pragma unroll
        for (int it = 0; it < 4; it++) {
            int i = tid + it * 256;
            int r = i >> 4, c = i & 15;
            sA[c][r] = A[(long long)(m0 + r) * lda + (k0 + c)];
        }
        if (TRANSB) {
#pragma unroll
            for (int it = 0; it < 4; it++) {
                int i = tid + it * 256;
                int r = i >> 4, c = i & 15;
                sB[c][r] = B[(long long)(n0 + r) * ldb + (k0 + c)];
            }
        } else {
#pragma unroll
            for (int it = 0; it < 4; it++) {
                int i = tid + it * 256;
                int kk = i >> 6, n = i & 63;
                sB[kk][n] = B[(long long)(k0 + kk) * ldb + (n0 + n)];
            }
        }
        __syncthreads();
#pragma unroll
        for (int kk = 0; kk < 16; kk++) {
            float a[4], b[4];
#pragma unroll
            for (int i = 0; i < 4; i++) a[i] = sA[kk][ty * 4 + i];
#pragma unroll
            for (int j = 0; j < 4; j++) b[j] = sB[kk][tx * 4 + j];
#pragma unroll
            for (int i = 0; i < 4; i++)
#pragma unroll
                for (int j = 0; j < 4; j++) acc[i][j] += a[i] * b[j];
        }
        __syncthreads();
    }
#pragma unroll
    for (int i = 0; i < 4; i++)
#pragma unroll
        for (int j = 0; j < 4; j++)
            C[(long long)(m0 + ty * 4 + i) * ldc + (n0 + tx * 4 + j)] = acc[i][j];
}

// ---------------- RMSNorm (one CTA per row) -----------------------------------
__global__ __launch_bounds__(256)
void rmsnorm_k(const float* __restrict__ in, int ldin, const float* __restrict__ w,
               float* __restrict__ out, int ldout, int W)
{
    int row = blockIdx.x;
    const float* x = in + (long long)row * ldin;
    float ss = 0.f;
    for (int i = threadIdx.x; i < W; i += 256) { float v = x[i]; ss += v * v; }
#pragma unroll
    for (int o = 16; o > 0; o >>= 1) ss += __shfl_xor_sync(0xffffffffu, ss, o);
    __shared__ float red[8];
    if ((threadIdx.x & 31) == 0) red[threadIdx.x >> 5] = ss;
    __syncthreads();
    float tot = 0.f;
#pragma unroll
    for (int j = 0; j < 8; j++) tot += red[j];
    float sc = rsqrtf(tot / (float)W + 1e-6f);
    float* o = out + (long long)row * ldout;
    for (int i = threadIdx.x; i < W; i += 256) o[i] = x[i] * sc * w[i];
}

// ---------------- RoPE tables (double trig on fp32-rounded phase) --------------
__global__ void rope_table_k(float* __restrict__ ctab, float* __restrict__ stab)
{
    int idx = blockIdx.x * blockDim.x + threadIdx.x;
    if (idx >= SEQ * 32) return;
    int s = idx >> 5, i = idx & 31;
    float invf = (float)pow(10000.0, -((double)i / 32.0));
    float f = (float)s * invf;            // matches jax fp32 outer(t, inv_freq)
    double fd = (double)f;
    ctab[idx] = (float)cos(fd);
    stab[idx] = (float)sin(fd);
}

__global__ void rope_kpe_k(const float* __restrict__ kva, float* __restrict__ kcat,
                           const float* __restrict__ ctab, const float* __restrict__ stab)
{
    int idx = blockIdx.x * blockDim.x + threadIdx.x;
    if (idx >= SEQ * 32) return;
    int s = idx >> 5, i = idx & 31;
    float c = ctab[idx], sn = stab[idx];
    const float* in = kva + (long long)s * DCAT + KVL;
    float* out = kcat + (long long)s * DCAT + KVL;
    float x0 = in[2 * i], x1 = in[2 * i + 1];
    out[2 * i]     = x0 * c - x1 * sn;
    out[2 * i + 1] = x0 * sn + x1 * c;
}

__global__ void rope_qpe_k(const float* __restrict__ q, float* __restrict__ qcat,
                           const float* __restrict__ ctab, const float* __restrict__ stab)
{
    int idx = blockIdx.x * blockDim.x + threadIdx.x;
    if (idx >= NH * SEQ * 32) return;
    int i = idx & 31;
    int s = (idx >> 5) & (SEQ - 1);
    int h = idx >> 17;
    float c = ctab[(s << 5) + i], sn = stab[(s << 5) + i];
    const float* in = q + (long long)s * (NH * QKH) + h * QKH + NOPE;
    float* out = qcat + ((long long)h * SEQ + s) * DCAT + KVL;
    float x0 = in[2 * i], x1 = in[2 * i + 1];
    out[2 * i]     = x0 * c - x1 * sn;
    out[2 * i + 1] = x0 * sn + x1 * c;
}

// ---------------- Flash attention (MQA, d_qk=576, d_v=512, causal) -------------
// Grid: (SEQ/32, NH). 256 threads = 8 warps; warp w owns query rows 4w..4w+3.
// Lane n computes scores S[m][n] for the 32-key tile; O acc lives in registers
// with d = lane + 32*jj. Q tile and K tile fully resident in smem.
__global__ __launch_bounds__(256)
void mla_attn_k(const float* __restrict__ qcat, const float* __restrict__ kcat,
                float* __restrict__ ctx)
{
    extern __shared__ float sm[];
    float (*sQ)[580] = (float (*)[580])sm;
    float (*sK)[580] = (float (*)[580])(sm + 32 * 580);
    const int h = blockIdx.y;
    const int qb = (int)gridDim.x - 1 - (int)blockIdx.x;  // longest blocks first
    const int tid = threadIdx.x;
    const int warp = tid >> 5, lane = tid & 31;
    const float* Q = qcat + ((long long)h * SEQ + (long long)qb * 32) * DCAT;

    for (int i = tid; i < 32 * 144; i += 256) {
        int r = i / 144, c = i - r * 144;
        *(float4*)(&sQ[r][c * 4]) = *(const float4*)(&Q[(long long)r * DCAT + c * 4]);
    }

    float acc[4][16];
#pragma unroll
    for (int mi = 0; mi < 4; mi++)
#pragma unroll
        for (int jj = 0; jj < 16; jj++) acc[mi][jj] = 0.f;
    float rm[4], rl[4];
#pragma unroll
    for (int mi = 0; mi < 4; mi++) { rm[mi] = -1e30f; rl[mi] = 0.f; }
    const int m0 = warp * 4;
    int qrow[4];
#pragma unroll
    for (int mi = 0; mi < 4; mi++) qrow[mi] = qb * 32 + m0 + mi;

    for (int kt = 0; kt <= qb; kt++) {
        __syncthreads();   // previous tile's PV done before overwriting sK
        const float* Kp = kcat + (long long)kt * 32 * DCAT;
        for (int i = tid; i < 32 * 144; i += 256) {
            int r = i / 144, c = i - r * 144;
            *(float4*)(&sK[r][c * 4]) = *(const float4*)(&Kp[(long long)r * DCAT + c * 4]);
        }
        __syncthreads();

        // ---- scores: S[m0+mi][lane] over 576 dims ----
        float s0 = 0.f, s1 = 0.f, s2 = 0.f, s3 = 0.f;
#pragma unroll 4
        for (int c = 0; c < 144; c++) {
            float4 kv = *(const float4*)(&sK[lane][c * 4]);
            float4 q0 = *(const float4*)(&sQ[m0 + 0][c * 4]);
            float4 q1 = *(const float4*)(&sQ[m0 + 1][c * 4]);
            float4 q2 = *(const float4*)(&sQ[m0 + 2][c * 4]);
            float4 q3 = *(const float4*)(&sQ[m0 + 3][c * 4]);
            s0 += q0.x * kv.x + q0.y * kv.y + q0.z * kv.z + q0.w * kv.w;
            s1 += q1.x * kv.x + q1.y * kv.y + q1.z * kv.z + q1.w * kv.w;
            s2 += q2.x * kv.x + q2.y * kv.y + q2.z * kv.z + q2.w * kv.w;
            s3 += q3.x * kv.x + q3.y * kv.y + q3.z * kv.z + q3.w * kv.w;
        }
        float sv[4] = {s0, s1, s2, s3};
        const int nglob = kt * 32 + lane;
        float preg[4];
#pragma unroll
        for (int mi = 0; mi < 4; mi++) {
            float vq = (nglob <= qrow[mi]) ? sv[mi] * SCALE_F : -1e30f;
            float mx = vq;
#pragma unroll
            for (int o = 16; o > 0; o >>= 1) mx = fmaxf(mx, __shfl_xor_sync(0xffffffffu, mx, o));
            float mnew = fmaxf(rm[mi], mx);
            float p = expf(vq - mnew);
            float corr = expf(rm[mi] - mnew);
            float ps = p;
#pragma unroll
            for (int o = 16; o > 0; o >>= 1) ps += __shfl_xor_sync(0xffffffffu, ps, o);
            rl[mi] = rl[mi] * corr + ps;
            rm[mi] = mnew;
#pragma unroll
            for (int jj = 0; jj < 16; jj++) acc[mi][jj] *= corr;
            preg[mi] = p;
        }

        // ---- PV: acc[m][d] += P[m][n] * V[n][d] (V = first 512 cols of sK) ----
#pragma unroll 2
        for (int n = 0; n < 32; n++) {
            float p0 = __shfl_sync(0xffffffffu, preg[0], n);
            float p1 = __shfl_sync(0xffffffffu, preg[1], n);
            float p2 = __shfl_sync(0xffffffffu, preg[2], n);
            float p3 = __shfl_sync(0xffffffffu, preg[3], n);
            const float* vrow = &sK[n][lane];
#pragma unroll
            for (int jj = 0; jj < 16; jj++) {
                float vv = vrow[32 * jj];
                acc[0][jj] += p0 * vv;
                acc[1][jj] += p1 * vv;
                acc[2][jj] += p2 * vv;
                acc[3][jj] += p3 * vv;
            }
        }
    }

#pragma unroll
    for (int mi = 0; mi < 4; mi++) {
        float inv = 1.f / rl[mi];
        float* o = ctx + ((long long)h * SEQ + qrow[mi]) * KVL + lane;
#pragma unroll
        for (int jj = 0; jj < 16; jj++) o[32 * jj] = acc[mi][jj] * inv;
    }
}

// ---------------- launch ------------------------------------------------------
extern "C" void kernel_launch(void* const* d_in, const int* in_sizes, int n_in,
                              void* d_out, int out_size)
{
    (void)in_sizes; (void)n_in; (void)out_size;
    const float* x       = (const float*)d_in[0];
    const float* wq_a    = (const float*)d_in[1];
    const float* q_norm  = (const float*)d_in[2];
    const float* wq_b    = (const float*)d_in[3];
    const float* wkv_a   = (const float*)d_in[4];
    const float* kv_norm = (const float*)d_in[5];
    const float* wkv_b   = (const float*)d_in[6];
    const float* wo      = (const float*)d_in[7];
    float* out = (float*)d_out;

    float *qa, *q, *kva, *kcat, *qcat, *ctx, *v, *ctab, *stab;
    cudaGetSymbolAddress((void**)&qa,   g_qa);
    cudaGetSymbolAddress((void**)&q,    g_q);
    cudaGetSymbolAddress((void**)&kva,  g_kva);
    cudaGetSymbolAddress((void**)&kcat, g_kcat);
    cudaGetSymbolAddress((void**)&qcat, g_qcat);
    cudaGetSymbolAddress((void**)&ctx,  g_ctx);
    cudaGetSymbolAddress((void**)&v,    g_v);
    cudaGetSymbolAddress((void**)&ctab, g_cos);
    cudaGetSymbolAddress((void**)&stab, g_sin);

    // RoPE tables
    rope_table_k<<<(SEQ * 32 + 255) / 256, 256>>>(ctab, stab);

    // qa = x @ wq_a^T ; rmsnorm ; q = qa @ wq_b^T
    gemm_k<true><<<dim3(QL / 64, SEQ / 64, 1), 256>>>(
        x, DIM, 0, wq_a, DIM, 0, qa, QL, 0, SEQ, QL, DIM);
    rmsnorm_k<<<SEQ, 256>>>(qa, QL, q_norm, qa, QL, QL);
    gemm_k<true><<<dim3(NH * QKH / 64, SEQ / 64, 1), 256>>>(
        qa, QL, 0, wq_b, QL, 0, q, NH * QKH, 0, SEQ, NH * QKH, QL);

    // kva = x @ wkv_a^T ; kcat = [rmsnorm(kv) | rope(k_pe)]
    gemm_k<true><<<dim3(DCAT / 64, SEQ / 64, 1), 256>>>(
        x, DIM, 0, wkv_a, DIM, 0, kva, DCAT, 0, SEQ, DCAT, DIM);
    rmsnorm_k<<<SEQ, 256>>>(kva, DCAT, kv_norm, kcat, DCAT, KVL);
    rope_kpe_k<<<(SEQ * 32 + 255) / 256, 256>>>(kva, kcat, ctab, stab);

    // qcat[h] = [ q_nope[h] @ wkv_b[h,:NOPE,:] | rope(q_pe[h]) ]   (batched NN)
    gemm_k<false><<<dim3(KVL / 64, SEQ / 64, NH), 256>>>(
        q, NH * QKH, QKH,
        wkv_b, KVL, (long long)(NOPE + 128) * KVL,
        qcat, DCAT, (long long)SEQ * DCAT,
        SEQ, KVL, NOPE);
    rope_qpe_k<<<(NH * SEQ * 32) / 256, 256>>>(q, qcat, ctab, stab);

    // attention
    cudaFuncSetAttribute(mla_attn_k, cudaFuncAttributeMaxDynamicSharedMemorySize, ATT_SMEM);
    mla_attn_k<<<dim3(SEQ / 32, NH), 256, ATT_SMEM>>>(qcat, kcat, ctx);

    // v[h] = ctx[h] @ wkv_b[h,NOPE:,:]^T   (batched TN), packed into [SEQ, NH*128]
    gemm_k<true><<<dim3(NOPE / 64, SEQ / 64, NH), 256>>>(
        ctx, KVL, (long long)SEQ * KVL,
        wkv_b + (long long)NOPE * KVL, KVL, (long long)(NOPE + 128) * KVL,
        v, DIM, NOPE,
        SEQ, NOPE, KVL);

    // out = v @ wo^T
    gemm_k<true><<<dim3(DIM / 64, SEQ / 64, 1), 256>>>(
        v, DIM, 0, wo, DIM, 0, out, DIM, 0, SEQ, DIM, DIM);
}

// round 3
// speedup vs baseline: 5.2956x; 5.2956x over previous
#include <cuda_runtime.h>
#include <math.h>
#include <stdint.h>

#define SEQ   4096
#define DIM   2048
#define NH    16
#define QL    1536
#define KVL   512
#define NOPE  128
#define QKH   192          // NOPE + ROPE
#define DCAT  576          // KVL + ROPE
#define SCALE_F 0.07216878364870322f  // 1/sqrt(192)

#define SMEM_GEMM(NT) ((2 * 128 + 2 * (NT)) * 36 * 4)

// ---------------- scratch (device globals; no allocations allowed) -------------
__device__ __align__(256) float g_xr[SEQ * DIM];
__device__ __align__(256) float g_wqa[QL * DIM];
__device__ __align__(256) float g_wqb[NH * QKH * QL];
__device__ __align__(256) float g_wka[DCAT * DIM];
__device__ __align__(256) float g_wbr[NH * 256 * KVL];
__device__ __align__(256) float g_wor[DIM * DIM];
__device__ __align__(256) float g_qa[SEQ * QL];
__device__ __align__(256) float g_q[SEQ * NH * QKH];
__device__ __align__(256) float g_kva[SEQ * DCAT];
__device__ __align__(256) float g_kcat[SEQ * DCAT];
__device__ __align__(256) float g_kcatT[DCAT * SEQ];
__device__ __align__(256) float g_qcat[NH * SEQ * DCAT];
__device__ __align__(256) float g_wbT[NH * KVL * NOPE];
__device__ __align__(256) float g_ctx[NH * SEQ * KVL];
__device__ __align__(256) float g_v[SEQ * DIM];
__device__ __align__(256) float g_cos[SEQ * 32];
__device__ __align__(256) float g_sin[SEQ * 32];
__device__ __align__(256) float g_S[(size_t)NH * SEQ * SEQ];   // 1 GB

// ---------------- helpers -------------------------------------------------------
__device__ __forceinline__ float tf32r(float x) {
    uint32_t o;
    asm("cvt.rna.tf32.f32 %0, %1;" : "=r"(o) : "f"(x));
    return __uint_as_float(o);
}
__device__ __forceinline__ uint32_t smem_u32(const void* p) {
    return (uint32_t)__cvta_generic_to_shared(p);
}
__device__ __forceinline__ void cpa16(uint32_t dst, const float* src) {
    asm volatile("cp.async.cg.shared.global [%0], [%1], 16;"
                 :: "r"(dst), "l"(__cvta_generic_to_global(src)) : "memory");
}
__device__ __forceinline__ void cp_commit() {
    asm volatile("cp.async.commit_group;" ::: "memory");
}
__device__ __forceinline__ void mma1688(float* c, const uint32_t* a, const uint32_t* b) {
    asm volatile(
        "mma.sync.aligned.m16n8k8.row.col.f32.tf32.tf32.f32 "
        "{%0,%1,%2,%3}, {%4,%5,%6,%7}, {%8,%9}, {%0,%1,%2,%3};"
        : "+f"(c[0]), "+f"(c[1]), "+f"(c[2]), "+f"(c[3])
        : "r"(a[0]), "r"(a[1]), "r"(a[2]), "r"(a[3]), "r"(b[0]), "r"(b[1]));
}

// ---------------- tf32 tensor-core GEMM: C[M,N] = A[M,K] @ B[N,K]^T -------------
// CTA tile 128 x NT, K-chunk 32, warps 2(M) x 4(N), warp tile 64 x NT/4.
// MODE 0: plain; 1: causal tile skip (n0 > m0); 2: K truncated to m0+128.
// RC: round C to tf32 (rna) on store.
template <int NT, int MODE, int RC>
__global__ __launch_bounds__(256, 1)
void gemm_mma(const float* __restrict__ A, int lda, long long strA,
              const float* __restrict__ B, int ldb, long long strB,
              float* __restrict__ C, int ldc, long long strC, int K)
{
    const int m0 = blockIdx.y * 128;
    const int n0 = blockIdx.x * NT;
    if (MODE == 1 && n0 > m0) return;
    const int Keff = (MODE == 2) ? (m0 + 128) : K;
    A += (long long)blockIdx.z * strA;
    B += (long long)blockIdx.z * strB;
    C += (long long)blockIdx.z * strC;

    extern __shared__ float sm[];
    float* sA = sm;                       // [2][128][36]
    float* sB = sm + 2 * 128 * 36;        // [2][NT][36]

    const int tid = threadIdx.x;
    const int lane = tid & 31, wid = tid >> 5;
    const int wm = wid & 1, wn = wid >> 1;
    const int gid = lane >> 2, tig = lane & 3;
    constexpr int NN = NT / 32;

    float acc[4][NN][4];
#pragma unroll
    for (int mi = 0; mi < 4; mi++)
#pragma unroll
        for (int ni = 0; ni < NN; ni++)
#pragma unroll
            for (int j = 0; j < 4; j++) acc[mi][ni][j] = 0.f;

    auto load_chunk = [&](int ic, int p) {
        const float* Ag = A + (long long)m0 * lda + ic * 32;
        uint32_t sAb = smem_u32(sA + p * 128 * 36);
#pragma unroll
        for (int it = 0; it < 4; it++) {
            int i = tid + it * 256;
            int r = i >> 3, c4 = i & 7;
            cpa16(sAb + (r * 36 + c4 * 4) * 4, Ag + (long long)r * lda + c4 * 4);
        }
        const float* Bg = B + (long long)n0 * ldb + ic * 32;
        uint32_t sBb = smem_u32(sB + p * NT * 36);
#pragma unroll
        for (int it = 0; it < NT / 32; it++) {
            int i = tid + it * 256;
            int r = i >> 3, c4 = i & 7;
            cpa16(sBb + (r * 36 + c4 * 4) * 4, Bg + (long long)r * ldb + c4 * 4);
        }
        cp_commit();
    };

    auto compute = [&](int p) {
        const float* cA = sA + p * 128 * 36 + (wm * 64 + gid) * 36 + tig;
        const float* cB = sB + p * NT * 36 + (wn * (NT / 4) + gid) * 36 + tig;
#pragma unroll
        for (int ks = 0; ks < 4; ks++) {
            const int k0 = ks * 8;
            uint32_t af[4][4], bf[NN][2];
#pragma unroll
            for (int mi = 0; mi < 4; mi++) {
                const float* ap = cA + mi * 16 * 36 + k0;
                af[mi][0] = __float_as_uint(ap[0]);
                af[mi][1] = __float_as_uint(ap[8 * 36]);
                af[mi][2] = __float_as_uint(ap[4]);
                af[mi][3] = __float_as_uint(ap[8 * 36 + 4]);
            }
#pragma unroll
            for (int ni = 0; ni < NN; ni++) {
                const float* bp = cB + ni * 8 * 36 + k0;
                bf[ni][0] = __float_as_uint(bp[0]);
                bf[ni][1] = __float_as_uint(bp[4]);
            }
#pragma unroll
            for (int mi = 0; mi < 4; mi++)
#pragma unroll
                for (int ni = 0; ni < NN; ni++)
                    mma1688(acc[mi][ni], af[mi], bf[ni]);
        }
    };

    const int nch = Keff >> 5;
    int issued = 0;
    load_chunk(0, 0); issued++;
    if (nch > 1) { load_chunk(1, 1); issued++; }
    for (int ic = 0; ic < nch; ic++) {
        const int p = ic & 1;
        if (issued - ic - 1 >= 1)
            asm volatile("cp.async.wait_group 1;" ::: "memory");
        else
            asm volatile("cp.async.wait_group 0;" ::: "memory");
        __syncthreads();
        compute(p);
        __syncthreads();
        if (ic + 2 < nch) { load_chunk(ic + 2, p); issued++; }
    }

    // epilogue: direct register -> gmem
#pragma unroll
    for (int mi = 0; mi < 4; mi++) {
        const int r0 = m0 + wm * 64 + mi * 16 + gid;
#pragma unroll
        for (int ni = 0; ni < NN; ni++) {
            const int c = n0 + wn * (NT / 4) + ni * 8 + tig * 2;
            float2 v0, v1;
            if (RC) {
                v0.x = tf32r(acc[mi][ni][0]); v0.y = tf32r(acc[mi][ni][1]);
                v1.x = tf32r(acc[mi][ni][2]); v1.y = tf32r(acc[mi][ni][3]);
            } else {
                v0.x = acc[mi][ni][0]; v0.y = acc[mi][ni][1];
                v1.x = acc[mi][ni][2]; v1.y = acc[mi][ni][3];
            }
            *(float2*)(C + (long long)r0 * ldc + c) = v0;
            *(float2*)(C + (long long)(r0 + 8) * ldc + c) = v1;
        }
    }
}

// ---------------- tf32 rounding copy --------------------------------------------
__global__ void round_copy_k(const float* __restrict__ in, float* __restrict__ out, int n)
{
    int i = blockIdx.x * 256 + threadIdx.x;
    if (i < n) out[i] = tf32r(in[i]);
}

// ---------------- RMSNorm (rounds output to tf32) --------------------------------
__global__ __launch_bounds__(256)
void rmsnorm_k(const float* __restrict__ in, int ldin, const float* __restrict__ w,
               float* __restrict__ out, int ldout, int W)
{
    int row = blockIdx.x;
    const float* x = in + (long long)row * ldin;
    float ss = 0.f;
    for (int i = threadIdx.x; i < W; i += 256) { float v = x[i]; ss += v * v; }
#pragma unroll
    for (int o = 16; o > 0; o >>= 1) ss += __shfl_xor_sync(0xffffffffu, ss, o);
    __shared__ float red[8];
    if ((threadIdx.x & 31) == 0) red[threadIdx.x >> 5] = ss;
    __syncthreads();
    float tot = 0.f;
#pragma unroll
    for (int j = 0; j < 8; j++) tot += red[j];
    float sc = rsqrtf(tot / (float)W + 1e-6f);
    float* o = out + (long long)row * ldout;
    for (int i = threadIdx.x; i < W; i += 256) o[i] = tf32r(x[i] * sc * w[i]);
}

// ---------------- RoPE ----------------------------------------------------------
__global__ void rope_table_k(float* __restrict__ ctab, float* __restrict__ stab)
{
    int idx = blockIdx.x * blockDim.x + threadIdx.x;
    if (idx >= SEQ * 32) return;
    int s = idx >> 5, i = idx & 31;
    float invf = (float)pow(10000.0, -((double)i / 32.0));
    float f = (float)s * invf;
    double fd = (double)f;
    ctab[idx] = (float)cos(fd);
    stab[idx] = (float)sin(fd);
}
__global__ void rope_kpe_k(const float* __restrict__ kva, float* __restrict__ kcat,
                           const float* __restrict__ ctab, const float* __restrict__ stab)
{
    int idx = blockIdx.x * blockDim.x + threadIdx.x;
    if (idx >= SEQ * 32) return;
    int s = idx >> 5, i = idx & 31;
    float c = ctab[idx], sn = stab[idx];
    const float* in = kva + (long long)s * DCAT + KVL;
    float* out = kcat + (long long)s * DCAT + KVL;
    float x0 = in[2 * i], x1 = in[2 * i + 1];
    out[2 * i]     = tf32r(x0 * c - x1 * sn);
    out[2 * i + 1] = tf32r(x0 * sn + x1 * c);
}
__global__ void rope_qpe_k(const float* __restrict__ q, float* __restrict__ qcat,
                           const float* __restrict__ ctab, const float* __restrict__ stab)
{
    int idx = blockIdx.x * blockDim.x + threadIdx.x;
    if (idx >= NH * SEQ * 32) return;
    int i = idx & 31;
    int s = (idx >> 5) & (SEQ - 1);
    int h = idx >> 17;
    float c = ctab[(s << 5) + i], sn = stab[(s << 5) + i];
    const float* in = q + (long long)s * (NH * QKH) + h * QKH + NOPE;
    float* out = qcat + ((long long)h * SEQ + s) * DCAT + KVL;
    float x0 = in[2 * i], x1 = in[2 * i + 1];
    out[2 * i]     = tf32r(x0 * c - x1 * sn);
    out[2 * i + 1] = tf32r(x0 * sn + x1 * c);
}

// ---------------- transposes ----------------------------------------------------
__global__ void transpose_kcat_k(const float* __restrict__ in, float* __restrict__ out)
{
    int idx = blockIdx.x * 256 + threadIdx.x;   // out-linear [c][t]
    if (idx >= DCAT * SEQ) return;
    int c = idx >> 12, t = idx & (SEQ - 1);
    out[idx] = in[(long long)t * DCAT + c];
}
__global__ void transpose_wb_k(const float* __restrict__ w, float* __restrict__ wt)
{
    int idx = blockIdx.x * 256 + threadIdx.x;   // out-linear [h][c][d]
    if (idx >= NH * KVL * NOPE) return;
    int h = idx >> 16, r = idx & 65535;
    int c = r >> 7, d = r & 127;
    wt[idx] = tf32r(w[((long long)(h * 256 + d)) * 512 + c]);
}

// ---------------- causal softmax (in place, scale fused, tf32-rounded) ----------
__global__ __launch_bounds__(256)
void softmax_causal_k(float* __restrict__ S)
{
    int h = blockIdx.y;
    int s = blockIdx.x * 8 + (threadIdx.x >> 5);
    int lane = threadIdx.x & 31;
    float* row = S + ((size_t)h * SEQ + s) * SEQ;
    int n = s + 1;
    float m = -1e30f;
    for (int t = lane; t < n; t += 32) m = fmaxf(m, row[t]);
#pragma unroll
    for (int o = 16; o > 0; o >>= 1) m = fmaxf(m, __shfl_xor_sync(0xffffffffu, m, o));
    float l = 0.f;
    for (int t = lane; t < n; t += 32) {
        float e = expf((row[t] - m) * SCALE_F);
        row[t] = e;
        l += e;
    }
#pragma unroll
    for (int o = 16; o > 0; o >>= 1) l += __shfl_xor_sync(0xffffffffu, l, o);
    float inv = 1.f / l;
    for (int t = lane; t < n; t += 32) row[t] = tf32r(row[t] * inv);
    int bnd = ((s >> 7) + 1) << 7;              // zero-fill to 128-tile boundary
    for (int t = n + lane; t < bnd; t += 32) row[t] = 0.f;
}

// ---------------- launch --------------------------------------------------------
extern "C" void kernel_launch(void* const* d_in, const int* in_sizes, int n_in,
                              void* d_out, int out_size)
{
    (void)in_sizes; (void)n_in; (void)out_size;
    const float* x       = (const float*)d_in[0];
    const float* wq_a    = (const float*)d_in[1];
    const float* q_norm  = (const float*)d_in[2];
    const float* wq_b    = (const float*)d_in[3];
    const float* wkv_a   = (const float*)d_in[4];
    const float* kv_norm = (const float*)d_in[5];
    const float* wkv_b   = (const float*)d_in[6];
    const float* wo      = (const float*)d_in[7];
    float* out = (float*)d_out;

    float *xr, *wqa, *wqb, *wka, *wbr, *wor;
    float *qa, *q, *kva, *kcat, *kcatT, *qcat, *wbT, *ctx, *v, *ctab, *stab, *S;
    cudaGetSymbolAddress((void**)&xr,    g_xr);
    cudaGetSymbolAddress((void**)&wqa,   g_wqa);
    cudaGetSymbolAddress((void**)&wqb,   g_wqb);
    cudaGetSymbolAddress((void**)&wka,   g_wka);
    cudaGetSymbolAddress((void**)&wbr,   g_wbr);
    cudaGetSymbolAddress((void**)&wor,   g_wor);
    cudaGetSymbolAddress((void**)&qa,    g_qa);
    cudaGetSymbolAddress((void**)&q,     g_q);
    cudaGetSymbolAddress((void**)&kva,   g_kva);
    cudaGetSymbolAddress((void**)&kcat,  g_kcat);
    cudaGetSymbolAddress((void**)&kcatT, g_kcatT);
    cudaGetSymbolAddress((void**)&qcat,  g_qcat);
    cudaGetSymbolAddress((void**)&wbT,   g_wbT);
    cudaGetSymbolAddress((void**)&ctx,   g_ctx);
    cudaGetSymbolAddress((void**)&v,     g_v);
    cudaGetSymbolAddress((void**)&ctab,  g_cos);
    cudaGetSymbolAddress((void**)&stab,  g_sin);
    cudaGetSymbolAddress((void**)&S,     g_S);

    cudaFuncSetAttribute(gemm_mma<256,0,1>, cudaFuncAttributeMaxDynamicSharedMemorySize, SMEM_GEMM(256));
    cudaFuncSetAttribute(gemm_mma<256,0,0>, cudaFuncAttributeMaxDynamicSharedMemorySize, SMEM_GEMM(256));
    cudaFuncSetAttribute(gemm_mma<256,1,0>, cudaFuncAttributeMaxDynamicSharedMemorySize, SMEM_GEMM(256));
    cudaFuncSetAttribute(gemm_mma<256,2,1>, cudaFuncAttributeMaxDynamicSharedMemorySize, SMEM_GEMM(256));
    cudaFuncSetAttribute(gemm_mma<128,0,1>, cudaFuncAttributeMaxDynamicSharedMemorySize, SMEM_GEMM(128));
    cudaFuncSetAttribute(gemm_mma<64,0,0>,  cudaFuncAttributeMaxDynamicSharedMemorySize, SMEM_GEMM(64));

    // ---- round inputs to tf32 (rna, unbiased) ----
    round_copy_k<<<(SEQ * DIM + 255) / 256, 256>>>(x, xr, SEQ * DIM);
    round_copy_k<<<(QL * DIM + 255) / 256, 256>>>(wq_a, wqa, QL * DIM);
    round_copy_k<<<(NH * QKH * QL + 255) / 256, 256>>>(wq_b, wqb, NH * QKH * QL);
    round_copy_k<<<(DCAT * DIM + 255) / 256, 256>>>(wkv_a, wka, DCAT * DIM);
    round_copy_k<<<(NH * 256 * KVL + 255) / 256, 256>>>(wkv_b, wbr, NH * 256 * KVL);
    round_copy_k<<<(DIM * DIM + 255) / 256, 256>>>(wo, wor, DIM * DIM);
    rope_table_k<<<(SEQ * 32 + 255) / 256, 256>>>(ctab, stab);
    transpose_wb_k<<<(NH * KVL * NOPE + 255) / 256, 256>>>(wkv_b, wbT);

    // qa = x @ wq_a^T ; rmsnorm ; q = qa @ wq_b^T
    gemm_mma<256,0,1><<<dim3(QL / 256, 32, 1), 256, SMEM_GEMM(256)>>>(
        xr, DIM, 0, wqa, DIM, 0, qa, QL, 0, DIM);
    rmsnorm_k<<<SEQ, 256>>>(qa, QL, q_norm, qa, QL, QL);
    gemm_mma<256,0,1><<<dim3(NH * QKH / 256, 32, 1), 256, SMEM_GEMM(256)>>>(
        qa, QL, 0, wqb, QL, 0, q, NH * QKH, 0, QL);

    // kva = x @ wkv_a^T ; kcat = [rmsnorm | rope]
    gemm_mma<64,0,0><<<dim3(DCAT / 64, 32, 1), 256, SMEM_GEMM(64)>>>(
        xr, DIM, 0, wka, DIM, 0, kva, DCAT, 0, DIM);
    rmsnorm_k<<<SEQ, 256>>>(kva, DCAT, kv_norm, kcat, DCAT, KVL);
    rope_kpe_k<<<(SEQ * 32 + 255) / 256, 256>>>(kva, kcat, ctab, stab);
    transpose_kcat_k<<<(DCAT * SEQ + 255) / 256, 256>>>(kcat, kcatT);

    // qcat[h][:, :512] = q_nope[h] @ wbT[h]^T
    gemm_mma<256,0,1><<<dim3(KVL / 256, 32, NH), 256, SMEM_GEMM(256)>>>(
        q, NH * QKH, QKH,
        wbT, NOPE, (long long)KVL * NOPE,
        qcat, DCAT, (long long)SEQ * DCAT, NOPE);
    rope_qpe_k<<<(NH * SEQ * 32) / 256, 256>>>(q, qcat, ctab, stab);

    // scores (causal tiles only)
    gemm_mma<256,1,0><<<dim3(SEQ / 256, 32, NH), 256, SMEM_GEMM(256)>>>(
        qcat, DCAT, (long long)SEQ * DCAT,
        kcat, DCAT, 0,
        S, SEQ, (long long)SEQ * SEQ, DCAT);

    softmax_causal_k<<<dim3(SEQ / 8, NH), 256>>>(S);

    // ctx = P @ kv  (K truncated to m0+128 per tile row)
    gemm_mma<256,2,1><<<dim3(KVL / 256, 32, NH), 256, SMEM_GEMM(256)>>>(
        S, SEQ, (long long)SEQ * SEQ,
        kcatT, SEQ, 0,
        ctx, KVL, (long long)SEQ * KVL, SEQ);

    // v[h] = ctx[h] @ wkv_b[h, NOPE:, :]^T, packed into [SEQ, NH*128]
    gemm_mma<128,0,1><<<dim3(1, 32, NH), 256, SMEM_GEMM(128)>>>(
        ctx, KVL, (long long)SEQ * KVL,
        wbr + (long long)NOPE * KVL, KVL, (long long)(NOPE + 128) * KVL,
        v, DIM, NOPE, KVL);

    // out = v @ wo^T
    gemm_mma<256,0,0><<<dim3(DIM / 256, 32, 1), 256, SMEM_GEMM(256)>>>(
        v, DIM, 0, wor, DIM, 0, out, DIM, 0, DIM);
}

// round 4
// speedup vs baseline: 9.2147x; 1.7401x over previous
#include <cuda_runtime.h>
#include <cuda_fp16.h>
#include <math.h>
#include <stdint.h>

#define SEQ   4096
#define DIM   2048
#define NH    16
#define QL    1536
#define KVL   512
#define NOPE  128
#define QKH   192          // NOPE + ROPE
#define DCAT  576          // KVL + ROPE
#define SCALE_F 0.07216878364870322f  // 1/sqrt(192)

#define SMEM_H(NT) ((2 * 128 + 2 * (NT)) * 72 * 2)

// ---------------- scratch (device globals; no allocations allowed) -------------
__device__ __align__(256) __half g_xh[SEQ * DIM];
__device__ __align__(256) __half g_wqa[QL * DIM];
__device__ __align__(256) __half g_wqb[NH * QKH * QL];
__device__ __align__(256) __half g_wka[DCAT * DIM];
__device__ __align__(256) __half g_wbr[NH * 256 * KVL];     // full wkv_b in fp16
__device__ __align__(256) __half g_woh[DIM * DIM];
__device__ __align__(256) __half g_wbT[NH * KVL * NOPE];    // [h][c][d]
__device__ __align__(256) __half g_qa[SEQ * QL];
__device__ __align__(256) __half g_q[SEQ * NH * QKH];
__device__ __align__(256) __half g_kva[SEQ * DCAT];
__device__ __align__(256) __half g_kcat[SEQ * DCAT];
__device__ __align__(256) __half g_kcatT[KVL * SEQ];        // [c][t], c<512
__device__ __align__(256) __half g_qcat[NH * SEQ * DCAT];
__device__ __align__(256) __half g_ctx[NH * SEQ * KVL];
__device__ __align__(256) __half g_v[SEQ * DIM];
__device__ __align__(256) float  g_cos[SEQ * 32];
__device__ __align__(256) float  g_sin[SEQ * 32];
__device__ __align__(256) float  g_S[(size_t)NH * SEQ * SEQ];   // raw scores fp32
__device__ __align__(256) __half g_P[(size_t)NH * SEQ * SEQ];   // probs fp16

// ---------------- helpers -------------------------------------------------------
__device__ __forceinline__ uint32_t smem_u32(const void* p) {
    return (uint32_t)__cvta_generic_to_shared(p);
}
__device__ __forceinline__ void cpa16(uint32_t dst, const void* src) {
    asm volatile("cp.async.cg.shared.global [%0], [%1], 16;"
                 :: "r"(dst), "l"(__cvta_generic_to_global(src)) : "memory");
}
__device__ __forceinline__ void cp_commit() {
    asm volatile("cp.async.commit_group;" ::: "memory");
}
__device__ __forceinline__ void mma16816(float* c, const uint32_t* a, const uint32_t* b) {
    asm volatile(
        "mma.sync.aligned.m16n8k16.row.col.f32.f16.f16.f32 "
        "{%0,%1,%2,%3}, {%4,%5,%6,%7}, {%8,%9}, {%0,%1,%2,%3};"
        : "+f"(c[0]), "+f"(c[1]), "+f"(c[2]), "+f"(c[3])
        : "r"(a[0]), "r"(a[1]), "r"(a[2]), "r"(a[3]), "r"(b[0]), "r"(b[1]));
}

// ---------------- fp16 tensor-core GEMM: C[M,N] = A[M,K] @ B[N,K]^T --------------
// A,B fp16 row-major. CTA tile 128 x NT, K-chunk 64, warps 2(M) x 4(N).
// MODE 0: plain; 1: causal tile skip (n0 > m0); 2: K truncated to m0+128.
// HOUT: 1 -> fp16 C, 0 -> fp32 C.
template <int NT, int MODE, int HOUT>
__global__ __launch_bounds__(256, 1)
void gemm_h(const __half* __restrict__ A, int lda, long long strA,
            const __half* __restrict__ B, int ldb, long long strB,
            void* __restrict__ Cv, int ldc, long long strC, int K)
{
    const int m0 = blockIdx.y * 128;
    const int n0 = blockIdx.x * NT;
    if (MODE == 1 && n0 > m0) return;
    const int Keff = (MODE == 2) ? (m0 + 128) : K;
    A += (long long)blockIdx.z * strA;
    B += (long long)blockIdx.z * strB;

    extern __shared__ __half sh[];
    __half* sA = sh;                      // [2][128][72]
    __half* sB = sh + 2 * 128 * 72;       // [2][NT][72]

    const int tid = threadIdx.x;
    const int lane = tid & 31, wid = tid >> 5;
    const int wm = wid & 1, wn = wid >> 1;
    const int gid = lane >> 2, tig = lane & 3;
    constexpr int NN = NT / 32;

    float acc[4][NN][4];
#pragma unroll
    for (int mi = 0; mi < 4; mi++)
#pragma unroll
        for (int ni = 0; ni < NN; ni++)
#pragma unroll
            for (int j = 0; j < 4; j++) acc[mi][ni][j] = 0.f;

    auto load_chunk = [&](int ic, int p) {
        const __half* Ag = A + (long long)m0 * lda + ic * 64;
        uint32_t sAb = smem_u32(sA + p * 128 * 72);
#pragma unroll
        for (int it = 0; it < 4; it++) {
            int i = tid + it * 256;
            int r = i >> 3, seg = i & 7;
            cpa16(sAb + (r * 72 + seg * 8) * 2, Ag + (long long)r * lda + seg * 8);
        }
        const __half* Bg = B + (long long)n0 * ldb + ic * 64;
        uint32_t sBb = smem_u32(sB + p * NT * 72);
#pragma unroll
        for (int it = 0; it < NT / 32; it++) {
            int i = tid + it * 256;
            int r = i >> 3, seg = i & 7;
            cpa16(sBb + (r * 72 + seg * 8) * 2, Bg + (long long)r * ldb + seg * 8);
        }
        cp_commit();
    };

    auto compute = [&](int p) {
        const __half* cA = sA + p * 128 * 72 + (wm * 64 + gid) * 72 + 2 * tig;
        const __half* cB = sB + p * NT * 72 + (wn * (NT / 4) + gid) * 72 + 2 * tig;
#pragma unroll
        for (int ks = 0; ks < 4; ks++) {
            const int k0 = ks * 16;
            uint32_t af[4][4], bf[NN][2];
#pragma unroll
            for (int mi = 0; mi < 4; mi++) {
                const __half* ap = cA + mi * 16 * 72 + k0;
                af[mi][0] = *(const uint32_t*)(ap);
                af[mi][1] = *(const uint32_t*)(ap + 8 * 72);
                af[mi][2] = *(const uint32_t*)(ap + 8);
                af[mi][3] = *(const uint32_t*)(ap + 8 * 72 + 8);
            }
#pragma unroll
            for (int ni = 0; ni < NN; ni++) {
                const __half* bp = cB + ni * 8 * 72 + k0;
                bf[ni][0] = *(const uint32_t*)(bp);
                bf[ni][1] = *(const uint32_t*)(bp + 8);
            }
#pragma unroll
            for (int mi = 0; mi < 4; mi++)
#pragma unroll
                for (int ni = 0; ni < NN; ni++)
                    mma16816(acc[mi][ni], af[mi], bf[ni]);
        }
    };

    const int nch = Keff >> 6;
    int issued = 0;
    load_chunk(0, 0); issued++;
    if (nch > 1) { load_chunk(1, 1); issued++; }
    for (int ic = 0; ic < nch; ic++) {
        const int p = ic & 1;
        if (issued - ic - 1 >= 1)
            asm volatile("cp.async.wait_group 1;" ::: "memory");
        else
            asm volatile("cp.async.wait_group 0;" ::: "memory");
        __syncthreads();
        compute(p);
        __syncthreads();
        if (ic + 2 < nch) { load_chunk(ic + 2, p); issued++; }
    }

    // epilogue
#pragma unroll
    for (int mi = 0; mi < 4; mi++) {
        const int r0 = m0 + wm * 64 + mi * 16 + gid;
#pragma unroll
        for (int ni = 0; ni < NN; ni++) {
            const int c = n0 + wn * (NT / 4) + ni * 8 + tig * 2;
            if (HOUT) {
                __half* C = (__half*)Cv + (long long)blockIdx.z * strC;
                __half2 v0 = __floats2half2_rn(acc[mi][ni][0], acc[mi][ni][1]);
                __half2 v1 = __floats2half2_rn(acc[mi][ni][2], acc[mi][ni][3]);
                *(__half2*)(C + (long long)r0 * ldc + c) = v0;
                *(__half2*)(C + (long long)(r0 + 8) * ldc + c) = v1;
            } else {
                float* C = (float*)Cv + (long long)blockIdx.z * strC;
                *(float2*)(C + (long long)r0 * ldc + c) =
                    make_float2(acc[mi][ni][0], acc[mi][ni][1]);
                *(float2*)(C + (long long)(r0 + 8) * ldc + c) =
                    make_float2(acc[mi][ni][2], acc[mi][ni][3]);
            }
        }
    }
}

// ---------------- converters ------------------------------------------------------
__global__ void cvt_k(const float* __restrict__ in, __half* __restrict__ out, int n)
{
    int i = blockIdx.x * 256 + threadIdx.x;
    if (i < n) out[i] = __float2half_rn(in[i]);
}
__global__ void cvt_wbT_k(const float* __restrict__ w, __half* __restrict__ wt)
{
    int idx = blockIdx.x * 256 + threadIdx.x;   // out-linear [h][c][d]
    if (idx >= NH * KVL * NOPE) return;
    int h = idx >> 16, r = idx & 65535;
    int c = r >> 7, d = r & 127;
    wt[idx] = __float2half_rn(w[((long long)(h * 256 + d)) * 512 + c]);
}
__global__ void transpose_kcat_k(const __half* __restrict__ in, __half* __restrict__ out)
{
    int idx = blockIdx.x * 256 + threadIdx.x;   // out-linear [c][t], c<512
    if (idx >= KVL * SEQ) return;
    int c = idx >> 12, t = idx & (SEQ - 1);
    out[idx] = in[(long long)t * DCAT + c];
}

// ---------------- RMSNorm (fp16 in/out, fp32 math) --------------------------------
__global__ __launch_bounds__(256)
void rmsnorm_k(const __half* __restrict__ in, int ldin, const float* __restrict__ w,
               __half* __restrict__ out, int ldout, int W)
{
    int row = blockIdx.x;
    const __half* x = in + (long long)row * ldin;
    float ss = 0.f;
    for (int i = threadIdx.x; i < W; i += 256) { float v = __half2float(x[i]); ss += v * v; }
#pragma unroll
    for (int o = 16; o > 0; o >>= 1) ss += __shfl_xor_sync(0xffffffffu, ss, o);
    __shared__ float red[8];
    if ((threadIdx.x & 31) == 0) red[threadIdx.x >> 5] = ss;
    __syncthreads();
    float tot = 0.f;
#pragma unroll
    for (int j = 0; j < 8; j++) tot += red[j];
    float sc = rsqrtf(tot / (float)W + 1e-6f);
    __half* o = out + (long long)row * ldout;
    for (int i = threadIdx.x; i < W; i += 256)
        o[i] = __float2half_rn(__half2float(x[i]) * sc * w[i]);
}

// ---------------- RoPE -------------------------------------------------------------
__global__ void rope_table_k(float* __restrict__ ctab, float* __restrict__ stab)
{
    int idx = blockIdx.x * blockDim.x + threadIdx.x;
    if (idx >= SEQ * 32) return;
    int s = idx >> 5, i = idx & 31;
    float invf = (float)pow(10000.0, -((double)i / 32.0));
    float f = (float)s * invf;
    double fd = (double)f;
    ctab[idx] = (float)cos(fd);
    stab[idx] = (float)sin(fd);
}
__global__ void rope_kpe_k(const __half* __restrict__ kva, __half* __restrict__ kcat,
                           const float* __restrict__ ctab, const float* __restrict__ stab)
{
    int idx = blockIdx.x * blockDim.x + threadIdx.x;
    if (idx >= SEQ * 32) return;
    int s = idx >> 5, i = idx & 31;
    float c = ctab[idx], sn = stab[idx];
    const __half* in = kva + (long long)s * DCAT + KVL;
    __half* out = kcat + (long long)s * DCAT + KVL;
    float x0 = __half2float(in[2 * i]), x1 = __half2float(in[2 * i + 1]);
    out[2 * i]     = __float2half_rn(x0 * c - x1 * sn);
    out[2 * i + 1] = __float2half_rn(x0 * sn + x1 * c);
}
__global__ void rope_qpe_k(const __half* __restrict__ q, __half* __restrict__ qcat,
                           const float* __restrict__ ctab, const float* __restrict__ stab)
{
    int idx = blockIdx.x * blockDim.x + threadIdx.x;
    if (idx >= NH * SEQ * 32) return;
    int i = idx & 31;
    int s = (idx >> 5) & (SEQ - 1);
    int h = idx >> 17;
    float c = ctab[(s << 5) + i], sn = stab[(s << 5) + i];
    const __half* in = q + (long long)s * (NH * QKH) + h * QKH + NOPE;
    __half* out = qcat + ((long long)h * SEQ + s) * DCAT + KVL;
    float x0 = __half2float(in[2 * i]), x1 = __half2float(in[2 * i + 1]);
    out[2 * i]     = __float2half_rn(x0 * c - x1 * sn);
    out[2 * i + 1] = __float2half_rn(x0 * sn + x1 * c);
}

// ---------------- causal softmax: fp32 scores -> fp16 probs ------------------------
__global__ __launch_bounds__(256)
void softmax_causal_k(const float* __restrict__ S, __half* __restrict__ P)
{
    int h = blockIdx.y;
    int s = blockIdx.x * 8 + (threadIdx.x >> 5);
    int lane = threadIdx.x & 31;
    const float* row = S + ((size_t)h * SEQ + s) * SEQ;
    __half* prow = P + ((size_t)h * SEQ + s) * SEQ;
    int n = s + 1;
    float m = -1e30f;
    for (int t = lane; t < n; t += 32) m = fmaxf(m, row[t]);
#pragma unroll
    for (int o = 16; o > 0; o >>= 1) m = fmaxf(m, __shfl_xor_sync(0xffffffffu, m, o));
    float l = 0.f;
    for (int t = lane; t < n; t += 32) l += expf((row[t] - m) * SCALE_F);
#pragma unroll
    for (int o = 16; o > 0; o >>= 1) l += __shfl_xor_sync(0xffffffffu, l, o);
    float inv = 1.f / l;
    for (int t = lane; t < n; t += 32)
        prow[t] = __float2half_rn(expf((row[t] - m) * SCALE_F) * inv);
    int bnd = ((s >> 7) + 1) << 7;   // zero-fill to 128-tile boundary
    for (int t = n + lane; t < bnd; t += 32) prow[t] = __float2half_rn(0.f);
}

// ---------------- launch ------------------------------------------------------------
extern "C" void kernel_launch(void* const* d_in, const int* in_sizes, int n_in,
                              void* d_out, int out_size)
{
    (void)in_sizes; (void)n_in; (void)out_size;
    const float* x       = (const float*)d_in[0];
    const float* wq_a    = (const float*)d_in[1];
    const float* q_norm  = (const float*)d_in[2];
    const float* wq_b    = (const float*)d_in[3];
    const float* wkv_a   = (const float*)d_in[4];
    const float* kv_norm = (const float*)d_in[5];
    const float* wkv_b   = (const float*)d_in[6];
    const float* wo      = (const float*)d_in[7];
    float* out = (float*)d_out;

    __half *xh, *wqa, *wqb, *wka, *wbr, *woh, *wbT;
    __half *qa, *q, *kva, *kcat, *kcatT, *qcat, *ctx, *v, *P;
    float *ctab, *stab, *S;
    cudaGetSymbolAddress((void**)&xh,    g_xh);
    cudaGetSymbolAddress((void**)&wqa,   g_wqa);
    cudaGetSymbolAddress((void**)&wqb,   g_wqb);
    cudaGetSymbolAddress((void**)&wka,   g_wka);
    cudaGetSymbolAddress((void**)&wbr,   g_wbr);
    cudaGetSymbolAddress((void**)&woh,   g_woh);
    cudaGetSymbolAddress((void**)&wbT,   g_wbT);
    cudaGetSymbolAddress((void**)&qa,    g_qa);
    cudaGetSymbolAddress((void**)&q,     g_q);
    cudaGetSymbolAddress((void**)&kva,   g_kva);
    cudaGetSymbolAddress((void**)&kcat,  g_kcat);
    cudaGetSymbolAddress((void**)&kcatT, g_kcatT);
    cudaGetSymbolAddress((void**)&qcat,  g_qcat);
    cudaGetSymbolAddress((void**)&ctx,   g_ctx);
    cudaGetSymbolAddress((void**)&v,     g_v);
    cudaGetSymbolAddress((void**)&ctab,  g_cos);
    cudaGetSymbolAddress((void**)&stab,  g_sin);
    cudaGetSymbolAddress((void**)&S,     g_S);
    cudaGetSymbolAddress((void**)&P,     g_P);

    cudaFuncSetAttribute(gemm_h<256,0,1>, cudaFuncAttributeMaxDynamicSharedMemorySize, SMEM_H(256));
    cudaFuncSetAttribute(gemm_h<256,0,0>, cudaFuncAttributeMaxDynamicSharedMemorySize, SMEM_H(256));
    cudaFuncSetAttribute(gemm_h<256,1,0>, cudaFuncAttributeMaxDynamicSharedMemorySize, SMEM_H(256));
    cudaFuncSetAttribute(gemm_h<256,2,1>, cudaFuncAttributeMaxDynamicSharedMemorySize, SMEM_H(256));
    cudaFuncSetAttribute(gemm_h<128,0,1>, cudaFuncAttributeMaxDynamicSharedMemorySize, SMEM_H(128));
    cudaFuncSetAttribute(gemm_h<64,0,1>,  cudaFuncAttributeMaxDynamicSharedMemorySize, SMEM_H(64));

    // ---- fp16 conversions of inputs ----
    cvt_k<<<(SEQ * DIM + 255) / 256, 256>>>(x, xh, SEQ * DIM);
    cvt_k<<<(QL * DIM + 255) / 256, 256>>>(wq_a, wqa, QL * DIM);
    cvt_k<<<(NH * QKH * QL + 255) / 256, 256>>>(wq_b, wqb, NH * QKH * QL);
    cvt_k<<<(DCAT * DIM + 255) / 256, 256>>>(wkv_a, wka, DCAT * DIM);
    cvt_k<<<(NH * 256 * KVL + 255) / 256, 256>>>(wkv_b, wbr, NH * 256 * KVL);
    cvt_k<<<(DIM * DIM + 255) / 256, 256>>>(wo, woh, DIM * DIM);
    cvt_wbT_k<<<(NH * KVL * NOPE + 255) / 256, 256>>>(wkv_b, wbT);
    rope_table_k<<<(SEQ * 32 + 255) / 256, 256>>>(ctab, stab);

    // qa = x @ wq_a^T ; rmsnorm ; q = qa @ wq_b^T
    gemm_h<256,0,1><<<dim3(QL / 256, 32, 1), 256, SMEM_H(256)>>>(
        xh, DIM, 0, wqa, DIM, 0, qa, QL, 0, DIM);
    rmsnorm_k<<<SEQ, 256>>>(qa, QL, q_norm, qa, QL, QL);
    gemm_h<256,0,1><<<dim3(NH * QKH / 256, 32, 1), 256, SMEM_H(256)>>>(
        qa, QL, 0, wqb, QL, 0, q, NH * QKH, 0, QL);

    // kva = x @ wkv_a^T ; kcat = [rmsnorm | rope]
    gemm_h<64,0,1><<<dim3(DCAT / 64, 32, 1), 256, SMEM_H(64)>>>(
        xh, DIM, 0, wka, DIM, 0, kva, DCAT, 0, DIM);
    rmsnorm_k<<<SEQ, 256>>>(kva, DCAT, kv_norm, kcat, DCAT, KVL);
    rope_kpe_k<<<(SEQ * 32 + 255) / 256, 256>>>(kva, kcat, ctab, stab);
    transpose_kcat_k<<<(KVL * SEQ + 255) / 256, 256>>>(kcat, kcatT);

    // qcat[h][:, :512] = q_nope[h] @ wbT[h]^T
    gemm_h<256,0,1><<<dim3(KVL / 256, 32, NH), 256, SMEM_H(256)>>>(
        q + 0, NH * QKH, QKH,
        wbT, NOPE, (long long)KVL * NOPE,
        qcat, DCAT, (long long)SEQ * DCAT, NOPE);
    rope_qpe_k<<<(NH * SEQ * 32) / 256, 256>>>(q, qcat, ctab, stab);

    // scores (causal tiles only, fp32 out)
    gemm_h<256,1,0><<<dim3(SEQ / 256, 32, NH), 256, SMEM_H(256)>>>(
        qcat, DCAT, (long long)SEQ * DCAT,
        kcat, DCAT, 0,
        S, SEQ, (long long)SEQ * SEQ, DCAT);

    softmax_causal_k<<<dim3(SEQ / 8, NH), 256>>>(S, P);

    // ctx = P @ kv  (K truncated to m0+128 per tile row)
    gemm_h<256,2,1><<<dim3(KVL / 256, 32, NH), 256, SMEM_H(256)>>>(
        P, SEQ, (long long)SEQ * SEQ,
        kcatT, SEQ, 0,
        ctx, KVL, (long long)SEQ * KVL, SEQ);

    // v[h] = ctx[h] @ wkv_b[h, NOPE:, :]^T, packed into [SEQ, NH*128]
    gemm_h<128,0,1><<<dim3(1, 32, NH), 256, SMEM_H(128)>>>(
        ctx, KVL, (long long)SEQ * KVL,
        wbr + (long long)NOPE * KVL, KVL, (long long)(NOPE + 128) * KVL,
        v, DIM, NOPE, KVL);

    // out = v @ wo^T (fp32 out)
    gemm_h<256,0,0><<<dim3(DIM / 256, 32, 1), 256, SMEM_H(256)>>>(
        v, DIM, 0, woh, DIM, 0, out, DIM, 0, DIM);
}

// round 5
// speedup vs baseline: 9.3024x; 1.0095x over previous
#include <cuda_runtime.h>
#include <cuda_fp16.h>
#include <math.h>
#include <stdint.h>

#define SEQ   4096
#define DIM   2048
#define NH    16
#define QL    1536
#define KVL   512
#define NOPE  128
#define QKH   192          // NOPE + ROPE
#define DCAT  576          // KVL + ROPE
#define SCALE_F 0.07216878364870322f  // 1/sqrt(192)

#define SMEM_H(NT) (3 * (128 + (NT)) * 72 * 2)

// ---------------- scratch (device globals; no allocations allowed) -------------
__device__ __align__(256) __half g_xh[SEQ * DIM];
__device__ __align__(256) __half g_wqa[QL * DIM];
__device__ __align__(256) __half g_wqb[NH * QKH * QL];
__device__ __align__(256) __half g_wka[DCAT * DIM];
__device__ __align__(256) __half g_wbr[NH * 256 * KVL];     // full wkv_b in fp16
__device__ __align__(256) __half g_woh[DIM * DIM];
__device__ __align__(256) __half g_wbT[NH * KVL * NOPE];    // [h][c][d]
__device__ __align__(256) __half g_qa[SEQ * QL];
__device__ __align__(256) __half g_q[SEQ * NH * QKH];
__device__ __align__(256) __half g_kva[SEQ * DCAT];
__device__ __align__(256) __half g_kcat[SEQ * DCAT];
__device__ __align__(256) __half g_kcatT[KVL * SEQ];        // [c][t], c<512
__device__ __align__(256) __half g_qcat[NH * SEQ * DCAT];
__device__ __align__(256) __half g_ctx[NH * SEQ * KVL];
__device__ __align__(256) __half g_v[SEQ * DIM];
__device__ __align__(256) float  g_cos[SEQ * 32];
__device__ __align__(256) float  g_sin[SEQ * 32];
__device__ __align__(256) float  g_S[(size_t)NH * SEQ * SEQ];   // raw scores fp32
__device__ __align__(256) __half g_P[(size_t)NH * SEQ * SEQ];   // probs fp16

// ---------------- helpers -------------------------------------------------------
__device__ __forceinline__ uint32_t smem_u32(const void* p) {
    return (uint32_t)__cvta_generic_to_shared(p);
}
__device__ __forceinline__ void cpa16(uint32_t dst, const void* src) {
    asm volatile("cp.async.cg.shared.global [%0], [%1], 16;"
                 :: "r"(dst), "l"(__cvta_generic_to_global(src)) : "memory");
}
__device__ __forceinline__ void cp_commit() {
    asm volatile("cp.async.commit_group;" ::: "memory");
}
__device__ __forceinline__ void ldmx4(uint32_t* r, uint32_t addr) {
    asm volatile("ldmatrix.sync.aligned.m8n8.x4.shared.b16 {%0,%1,%2,%3}, [%4];"
                 : "=r"(r[0]), "=r"(r[1]), "=r"(r[2]), "=r"(r[3]) : "r"(addr));
}
__device__ __forceinline__ void mma16816(float* c, const uint32_t* a, const uint32_t* b) {
    asm volatile(
        "mma.sync.aligned.m16n8k16.row.col.f32.f16.f16.f32 "
        "{%0,%1,%2,%3}, {%4,%5,%6,%7}, {%8,%9}, {%0,%1,%2,%3};"
        : "+f"(c[0]), "+f"(c[1]), "+f"(c[2]), "+f"(c[3])
        : "r"(a[0]), "r"(a[1]), "r"(a[2]), "r"(a[3]), "r"(b[0]), "r"(b[1]));
}

// ---------------- fp16 tensor-core GEMM: C[M,N] = A[M,K] @ B[N,K]^T --------------
// A,B fp16 row-major. CTA tile 128 x NT, K-chunk 64, 3-stage cp.async pipeline,
// ldmatrix fragment loads. Warps 2(M) x 4(N).
// MODE 0: plain; 1: causal tile skip (n0 > m0); 2: K truncated to m0+128.
// HOUT: 1 -> fp16 C, 0 -> fp32 C.
template <int NT, int MODE, int HOUT>
__global__ __launch_bounds__(256, 1)
void gemm_h(const __half* __restrict__ A, int lda, long long strA,
            const __half* __restrict__ B, int ldb, long long strB,
            void* __restrict__ Cv, int ldc, long long strC, int K)
{
    const int m0 = blockIdx.y * 128;
    const int n0 = blockIdx.x * NT;
    if (MODE == 1 && n0 > m0) return;
    const int Keff = (MODE == 2) ? (m0 + 128) : K;
    A += (long long)blockIdx.z * strA;
    B += (long long)blockIdx.z * strB;

    extern __shared__ __half sh[];
    __half* sA = sh;                      // [3][128][72]
    __half* sB = sh + 3 * 128 * 72;       // [3][NT][72]

    const int tid = threadIdx.x;
    const int lane = tid & 31, wid = tid >> 5;
    const int wm = wid & 1, wn = wid >> 1;
    const int gid = lane >> 2, tig = lane & 3;
    constexpr int NN = NT / 32;

    float acc[4][NN][4];
#pragma unroll
    for (int mi = 0; mi < 4; mi++)
#pragma unroll
        for (int ni = 0; ni < NN; ni++)
#pragma unroll
            for (int j = 0; j < 4; j++) acc[mi][ni][j] = 0.f;

    auto load_chunk = [&](int ic, int p) {
        const __half* Ag = A + (long long)m0 * lda + ic * 64;
        uint32_t sAb = smem_u32(sA + p * 128 * 72);
#pragma unroll
        for (int it = 0; it < 4; it++) {
            int i = tid + it * 256;
            int r = i >> 3, seg = i & 7;
            cpa16(sAb + (r * 72 + seg * 8) * 2, Ag + (long long)r * lda + seg * 8);
        }
        const __half* Bg = B + (long long)n0 * ldb + ic * 64;
        uint32_t sBb = smem_u32(sB + p * NT * 72);
#pragma unroll
        for (int it = 0; it < NT / 32; it++) {
            int i = tid + it * 256;
            int r = i >> 3, seg = i & 7;
            cpa16(sBb + (r * 72 + seg * 8) * 2, Bg + (long long)r * ldb + seg * 8);
        }
        cp_commit();
    };

    // ldmatrix per-thread source layouts (conflict-free with 72-half row stride):
    //  A x4: lanes 0-7 rows0-7@k0 | 8-15 rows8-15@k0 | 16-23 rows0-7@k8 | 24-31 rows8-15@k8
    //        -> regs a0,a1,a2,a3 exactly as mma16816 expects.
    //  B x4: lanes 0-7 n0-7@k0 | 8-15 n0-7@k8 | 16-23 n8-15@k0 | 24-31 n8-15@k8
    //        -> {b0,b1} of ni and {b0,b1} of ni+1.
    const int aRow = wm * 64 + (lane & 15);
    const int aK   = (lane >> 4) << 3;
    const int bRow = wn * (NT / 4) + ((lane >> 4) << 3) + (lane & 7);
    const int bK   = ((lane >> 3) & 1) << 3;

    auto compute = [&](int p) {
        const uint32_t aBase = smem_u32(sA + p * 128 * 72) + (aRow * 72 + aK) * 2;
        const uint32_t bBase = smem_u32(sB + p * NT * 72) + (bRow * 72 + bK) * 2;
#pragma unroll
        for (int ks = 0; ks < 4; ks++) {
            const int k0 = ks * 16;
            uint32_t af[4][4], bf[NN][2];
#pragma unroll
            for (int mi = 0; mi < 4; mi++)
                ldmx4(af[mi], aBase + (mi * 16 * 72 + k0) * 2);
#pragma unroll
            for (int n2 = 0; n2 < NN / 2; n2++) {
                uint32_t t[4];
                ldmx4(t, bBase + (n2 * 16 * 72 + k0) * 2);
                bf[2 * n2][0] = t[0]; bf[2 * n2][1] = t[1];
                bf[2 * n2 + 1][0] = t[2]; bf[2 * n2 + 1][1] = t[3];
            }
#pragma unroll
            for (int mi = 0; mi < 4; mi++)
#pragma unroll
                for (int ni = 0; ni < NN; ni++)
                    mma16816(acc[mi][ni], af[mi], bf[ni]);
        }
    };

    const int nch = Keff >> 6;
    load_chunk(0, 0);
    if (nch > 1) load_chunk(1, 1);
    for (int ic = 0; ic < nch; ic++) {
        const int p = ic % 3;
        if (ic + 1 < nch)
            asm volatile("cp.async.wait_group 1;" ::: "memory");
        else
            asm volatile("cp.async.wait_group 0;" ::: "memory");
        __syncthreads();
        if (ic + 2 < nch) load_chunk(ic + 2, (ic + 2) % 3);
        compute(p);
    }

    // epilogue
#pragma unroll
    for (int mi = 0; mi < 4; mi++) {
        const int r0 = m0 + wm * 64 + mi * 16 + gid;
#pragma unroll
        for (int ni = 0; ni < NN; ni++) {
            const int c = n0 + wn * (NT / 4) + ni * 8 + tig * 2;
            if (HOUT) {
                __half* C = (__half*)Cv + (long long)blockIdx.z * strC;
                *(__half2*)(C + (long long)r0 * ldc + c) =
                    __floats2half2_rn(acc[mi][ni][0], acc[mi][ni][1]);
                *(__half2*)(C + (long long)(r0 + 8) * ldc + c) =
                    __floats2half2_rn(acc[mi][ni][2], acc[mi][ni][3]);
            } else {
                float* C = (float*)Cv + (long long)blockIdx.z * strC;
                *(float2*)(C + (long long)r0 * ldc + c) =
                    make_float2(acc[mi][ni][0], acc[mi][ni][1]);
                *(float2*)(C + (long long)(r0 + 8) * ldc + c) =
                    make_float2(acc[mi][ni][2], acc[mi][ni][3]);
            }
        }
    }
}

// ---------------- converters ------------------------------------------------------
__global__ void cvt_k(const float* __restrict__ in, __half* __restrict__ out, int n)
{
    int i = blockIdx.x * 256 + threadIdx.x;
    if (i < n) out[i] = __float2half_rn(in[i]);
}
__global__ void cvt_wbT_k(const float* __restrict__ w, __half* __restrict__ wt)
{
    int idx = blockIdx.x * 256 + threadIdx.x;   // out-linear [h][c][d]
    if (idx >= NH * KVL * NOPE) return;
    int h = idx >> 16, r = idx & 65535;
    int c = r >> 7, d = r & 127;
    wt[idx] = __float2half_rn(w[((long long)(h * 256 + d)) * 512 + c]);
}
// tiled transpose kcat[:, :512] -> kcatT [c][t]
__global__ __launch_bounds__(256)
void transpose_kcat_k(const __half* __restrict__ in, __half* __restrict__ out)
{
    __shared__ __half tile[32][33];
    int ct = blockIdx.x * 32, tt = blockIdx.y * 32;
    int tx = threadIdx.x & 31, ty = threadIdx.x >> 5;
    for (int i = ty; i < 32; i += 8)
        tile[i][tx] = in[(long long)(tt + i) * DCAT + ct + tx];
    __syncthreads();
    for (int i = ty; i < 32; i += 8)
        out[(long long)(ct + i) * SEQ + tt + tx] = tile[tx][i];
}

// ---------------- RMSNorm (fp16 in/out, fp32 math) --------------------------------
__global__ __launch_bounds__(256)
void rmsnorm_k(const __half* __restrict__ in, int ldin, const float* __restrict__ w,
               __half* __restrict__ out, int ldout, int W)
{
    int row = blockIdx.x;
    const __half* x = in + (long long)row * ldin;
    float ss = 0.f;
    for (int i = threadIdx.x; i < W; i += 256) { float v = __half2float(x[i]); ss += v * v; }
#pragma unroll
    for (int o = 16; o > 0; o >>= 1) ss += __shfl_xor_sync(0xffffffffu, ss, o);
    __shared__ float red[8];
    if ((threadIdx.x & 31) == 0) red[threadIdx.x >> 5] = ss;
    __syncthreads();
    float tot = 0.f;
#pragma unroll
    for (int j = 0; j < 8; j++) tot += red[j];
    float sc = rsqrtf(tot / (float)W + 1e-6f);
    __half* o = out + (long long)row * ldout;
    for (int i = threadIdx.x; i < W; i += 256)
        o[i] = __float2half_rn(__half2float(x[i]) * sc * w[i]);
}

// ---------------- RoPE -------------------------------------------------------------
__global__ void rope_table_k(float* __restrict__ ctab, float* __restrict__ stab)
{
    int idx = blockIdx.x * blockDim.x + threadIdx.x;
    if (idx >= SEQ * 32) return;
    int s = idx >> 5, i = idx & 31;
    float invf = (float)pow(10000.0, -((double)i / 32.0));
    float f = (float)s * invf;
    double fd = (double)f;
    ctab[idx] = (float)cos(fd);
    stab[idx] = (float)sin(fd);
}
__global__ void rope_kpe_k(const __half* __restrict__ kva, __half* __restrict__ kcat,
                           const float* __restrict__ ctab, const float* __restrict__ stab)
{
    int idx = blockIdx.x * blockDim.x + threadIdx.x;
    if (idx >= SEQ * 32) return;
    int s = idx >> 5, i = idx & 31;
    float c = ctab[idx], sn = stab[idx];
    const __half* in = kva + (long long)s * DCAT + KVL;
    __half* out = kcat + (long long)s * DCAT + KVL;
    float x0 = __half2float(in[2 * i]), x1 = __half2float(in[2 * i + 1]);
    out[2 * i]     = __float2half_rn(x0 * c - x1 * sn);
    out[2 * i + 1] = __float2half_rn(x0 * sn + x1 * c);
}
__global__ void rope_qpe_k(const __half* __restrict__ q, __half* __restrict__ qcat,
                           const float* __restrict__ ctab, const float* __restrict__ stab)
{
    int idx = blockIdx.x * blockDim.x + threadIdx.x;
    if (idx >= NH * SEQ * 32) return;
    int i = idx & 31;
    int s = (idx >> 5) & (SEQ - 1);
    int h = idx >> 17;
    float c = ctab[(s << 5) + i], sn = stab[(s << 5) + i];
    const __half* in = q + (long long)s * (NH * QKH) + h * QKH + NOPE;
    __half* out = qcat + ((long long)h * SEQ + s) * DCAT + KVL;
    float x0 = __half2float(in[2 * i]), x1 = __half2float(in[2 * i + 1]);
    out[2 * i]     = __float2half_rn(x0 * c - x1 * sn);
    out[2 * i + 1] = __float2half_rn(x0 * sn + x1 * c);
}

// ---------------- causal softmax: fp32 scores -> fp16 probs ------------------------
__global__ __launch_bounds__(256)
void softmax_causal_k(const float* __restrict__ S, __half* __restrict__ P)
{
    int h = blockIdx.y;
    int s = blockIdx.x * 8 + (threadIdx.x >> 5);
    int lane = threadIdx.x & 31;
    const float* row = S + ((size_t)h * SEQ + s) * SEQ;
    __half* prow = P + ((size_t)h * SEQ + s) * SEQ;
    int n = s + 1;
    float m = -1e30f;
    for (int t = lane; t < n; t += 32) m = fmaxf(m, row[t]);
#pragma unroll
    for (int o = 16; o > 0; o >>= 1) m = fmaxf(m, __shfl_xor_sync(0xffffffffu, m, o));
    float l = 0.f;
    for (int t = lane; t < n; t += 32) l += expf((row[t] - m) * SCALE_F);
#pragma unroll
    for (int o = 16; o > 0; o >>= 1) l += __shfl_xor_sync(0xffffffffu, l, o);
    float inv = 1.f / l;
    for (int t = lane; t < n; t += 32)
        prow[t] = __float2half_rn(expf((row[t] - m) * SCALE_F) * inv);
    int bnd = ((s >> 7) + 1) << 7;   // zero-fill to 128-tile boundary
    for (int t = n + lane; t < bnd; t += 32) prow[t] = __float2half_rn(0.f);
}

// ---------------- launch ------------------------------------------------------------
extern "C" void kernel_launch(void* const* d_in, const int* in_sizes, int n_in,
                              void* d_out, int out_size)
{
    (void)in_sizes; (void)n_in; (void)out_size;
    const float* x       = (const float*)d_in[0];
    const float* wq_a    = (const float*)d_in[1];
    const float* q_norm  = (const float*)d_in[2];
    const float* wq_b    = (const float*)d_in[3];
    const float* wkv_a   = (const float*)d_in[4];
    const float* kv_norm = (const float*)d_in[5];
    const float* wkv_b   = (const float*)d_in[6];
    const float* wo      = (const float*)d_in[7];
    float* out = (float*)d_out;

    __half *xh, *wqa, *wqb, *wka, *wbr, *woh, *wbT;
    __half *qa, *q, *kva, *kcat, *kcatT, *qcat, *ctx, *v, *P;
    float *ctab, *stab, *S;
    cudaGetSymbolAddress((void**)&xh,    g_xh);
    cudaGetSymbolAddress((void**)&wqa,   g_wqa);
    cudaGetSymbolAddress((void**)&wqb,   g_wqb);
    cudaGetSymbolAddress((void**)&wka,   g_wka);
    cudaGetSymbolAddress((void**)&wbr,   g_wbr);
    cudaGetSymbolAddress((void**)&woh,   g_woh);
    cudaGetSymbolAddress((void**)&wbT,   g_wbT);
    cudaGetSymbolAddress((void**)&qa,    g_qa);
    cudaGetSymbolAddress((void**)&q,     g_q);
    cudaGetSymbolAddress((void**)&kva,   g_kva);
    cudaGetSymbolAddress((void**)&kcat,  g_kcat);
    cudaGetSymbolAddress((void**)&kcatT, g_kcatT);
    cudaGetSymbolAddress((void**)&qcat,  g_qcat);
    cudaGetSymbolAddress((void**)&ctx,   g_ctx);
    cudaGetSymbolAddress((void**)&v,     g_v);
    cudaGetSymbolAddress((void**)&ctab,  g_cos);
    cudaGetSymbolAddress((void**)&stab,  g_sin);
    cudaGetSymbolAddress((void**)&S,     g_S);
    cudaGetSymbolAddress((void**)&P,     g_P);

    cudaFuncSetAttribute(gemm_h<256,0,1>, cudaFuncAttributeMaxDynamicSharedMemorySize, SMEM_H(256));
    cudaFuncSetAttribute(gemm_h<256,0,0>, cudaFuncAttributeMaxDynamicSharedMemorySize, SMEM_H(256));
    cudaFuncSetAttribute(gemm_h<256,1,0>, cudaFuncAttributeMaxDynamicSharedMemorySize, SMEM_H(256));
    cudaFuncSetAttribute(gemm_h<256,2,1>, cudaFuncAttributeMaxDynamicSharedMemorySize, SMEM_H(256));
    cudaFuncSetAttribute(gemm_h<128,0,1>, cudaFuncAttributeMaxDynamicSharedMemorySize, SMEM_H(128));
    cudaFuncSetAttribute(gemm_h<64,0,1>,  cudaFuncAttributeMaxDynamicSharedMemorySize, SMEM_H(64));

    // ---- fp16 conversions of inputs ----
    cvt_k<<<(SEQ * DIM + 255) / 256, 256>>>(x, xh, SEQ * DIM);
    cvt_k<<<(QL * DIM + 255) / 256, 256>>>(wq_a, wqa, QL * DIM);
    cvt_k<<<(NH * QKH * QL + 255) / 256, 256>>>(wq_b, wqb, NH * QKH * QL);
    cvt_k<<<(DCAT * DIM + 255) / 256, 256>>>(wkv_a, wka, DCAT * DIM);
    cvt_k<<<(NH * 256 * KVL + 255) / 256, 256>>>(wkv_b, wbr, NH * 256 * KVL);
    cvt_k<<<(DIM * DIM + 255) / 256, 256>>>(wo, woh, DIM * DIM);
    cvt_wbT_k<<<(NH * KVL * NOPE + 255) / 256, 256>>>(wkv_b, wbT);
    rope_table_k<<<(SEQ * 32 + 255) / 256, 256>>>(ctab, stab);

    // qa = x @ wq_a^T ; rmsnorm ; q = qa @ wq_b^T
    gemm_h<256,0,1><<<dim3(QL / 256, 32, 1), 256, SMEM_H(256)>>>(
        xh, DIM, 0, wqa, DIM, 0, qa, QL, 0, DIM);
    rmsnorm_k<<<SEQ, 256>>>(qa, QL, q_norm, qa, QL, QL);
    gemm_h<256,0,1><<<dim3(NH * QKH / 256, 32, 1), 256, SMEM_H(256)>>>(
        qa, QL, 0, wqb, QL, 0, q, NH * QKH, 0, QL);

    // kva = x @ wkv_a^T ; kcat = [rmsnorm | rope]
    gemm_h<64,0,1><<<dim3(DCAT / 64, 32, 1), 256, SMEM_H(64)>>>(
        xh, DIM, 0, wka, DIM, 0, kva, DCAT, 0, DIM);
    rmsnorm_k<<<SEQ, 256>>>(kva, DCAT, kv_norm, kcat, DCAT, KVL);
    rope_kpe_k<<<(SEQ * 32 + 255) / 256, 256>>>(kva, kcat, ctab, stab);
    transpose_kcat_k<<<dim3(KVL / 32, SEQ / 32), 256>>>(kcat, kcatT);

    // qcat[h][:, :512] = q_nope[h] @ wbT[h]^T
    gemm_h<256,0,1><<<dim3(KVL / 256, 32, NH), 256, SMEM_H(256)>>>(
        q, NH * QKH, QKH,
        wbT, NOPE, (long long)KVL * NOPE,
        qcat, DCAT, (long long)SEQ * DCAT, NOPE);
    rope_qpe_k<<<(NH * SEQ * 32) / 256, 256>>>(q, qcat, ctab, stab);

    // scores (causal tiles only, fp32 out)
    gemm_h<256,1,0><<<dim3(SEQ / 256, 32, NH), 256, SMEM_H(256)>>>(
        qcat, DCAT, (long long)SEQ * DCAT,
        kcat, DCAT, 0,
        S, SEQ, (long long)SEQ * SEQ, DCAT);

    softmax_causal_k<<<dim3(SEQ / 8, NH), 256>>>(S, P);

    // ctx = P @ kv  (K truncated to m0+128 per tile row)
    gemm_h<256,2,1><<<dim3(KVL / 256, 32, NH), 256, SMEM_H(256)>>>(
        P, SEQ, (long long)SEQ * SEQ,
        kcatT, SEQ, 0,
        ctx, KVL, (long long)SEQ * KVL, SEQ);

    // v[h] = ctx[h] @ wkv_b[h, NOPE:, :]^T, packed into [SEQ, NH*128]
    gemm_h<128,0,1><<<dim3(1, 32, NH), 256, SMEM_H(128)>>>(
        ctx, KVL, (long long)SEQ * KVL,
        wbr + (long long)NOPE * KVL, KVL, (long long)(NOPE + 128) * KVL,
        v, DIM, NOPE, KVL);

    // out = v @ wo^T (fp32 out)
    gemm_h<256,0,0><<<dim3(DIM / 256, 32, 1), 256, SMEM_H(256)>>>(
        v, DIM, 0, woh, DIM, 0, out, DIM, 0, DIM);
}

// round 6
// speedup vs baseline: 13.7842x; 1.4818x over previous
#include <cuda_runtime.h>
#include <cuda_fp16.h>
#include <math.h>
#include <stdint.h>

#define SEQ   4096
#define DIM   2048
#define NH    16
#define QL    1536
#define KVL   512
#define NOPE  128
#define QKH   192          // NOPE + ROPE
#define DCAT  576          // KVL + ROPE
#define SCALE_F 0.07216878364870322f  // 1/sqrt(192)

#define SMEM_H(NT) (3 * (128 + (NT)) * 72 * 2)

// ---------------- scratch (device globals; no allocations allowed) -------------
__device__ __align__(256) __half g_xh[SEQ * DIM];
__device__ __align__(256) __half g_wqa[QL * DIM];
__device__ __align__(256) __half g_wqb[NH * QKH * QL];
__device__ __align__(256) __half g_wka[DCAT * DIM];
__device__ __align__(256) __half g_wbr[NH * 256 * KVL];     // full wkv_b fp16
__device__ __align__(256) __half g_woh[DIM * DIM];
__device__ __align__(256) __half g_qa[SEQ * QL];
__device__ __align__(256) __half g_q[SEQ * NH * QKH];       // [q_nope | rope(q_pe)] per head
__device__ __align__(256) __half g_kva[SEQ * DCAT];
__device__ __align__(256) __half g_kcat[SEQ * DCAT];        // [rms(kv) | rope(k_pe)]
__device__ __align__(256) __half g_khat[NH * SEQ * QKH];    // per-head [k_nope | k_pe]
__device__ __align__(256) __half g_vT[NH * NOPE * SEQ];     // per-head V^T [d][t]
__device__ __align__(256) __half g_v[SEQ * DIM];            // packed attention out
__device__ __align__(256) float  g_cos[SEQ * 32];
__device__ __align__(256) float  g_sin[SEQ * 32];
__device__ __align__(256) float  g_S[(size_t)NH * SEQ * SEQ];   // raw scores fp32
__device__ __align__(256) __half g_P[(size_t)NH * SEQ * SEQ];   // probs fp16

// ---------------- helpers -------------------------------------------------------
__device__ __forceinline__ uint32_t smem_u32(const void* p) {
    return (uint32_t)__cvta_generic_to_shared(p);
}
__device__ __forceinline__ void cpa16(uint32_t dst, const void* src) {
    asm volatile("cp.async.cg.shared.global [%0], [%1], 16;"
                 :: "r"(dst), "l"(__cvta_generic_to_global(src)) : "memory");
}
__device__ __forceinline__ void cp_commit() {
    asm volatile("cp.async.commit_group;" ::: "memory");
}
__device__ __forceinline__ void ldmx4(uint32_t* r, uint32_t addr) {
    asm volatile("ldmatrix.sync.aligned.m8n8.x4.shared.b16 {%0,%1,%2,%3}, [%4];"
                 : "=r"(r[0]), "=r"(r[1]), "=r"(r[2]), "=r"(r[3]) : "r"(addr));
}
__device__ __forceinline__ void mma16816(float* c, const uint32_t* a, const uint32_t* b) {
    asm volatile(
        "mma.sync.aligned.m16n8k16.row.col.f32.f16.f16.f32 "
        "{%0,%1,%2,%3}, {%4,%5,%6,%7}, {%8,%9}, {%0,%1,%2,%3};"
        : "+f"(c[0]), "+f"(c[1]), "+f"(c[2]), "+f"(c[3])
        : "r"(a[0]), "r"(a[1]), "r"(a[2]), "r"(a[3]), "r"(b[0]), "r"(b[1]));
}

// ---------------- fp16 tensor-core GEMM: C[M,N] = A[M,K] @ B[N,K]^T --------------
// CTA tile 128 x NT, K-chunk 64, 3-stage cp.async pipeline, ldmatrix frag loads.
// MODE 0: plain; 1: causal tile skip (n0 > m0); 2: K truncated to m0+128.
// HOUT: 1 -> fp16 C, 0 -> fp32 C.
template <int NT, int MODE, int HOUT>
__global__ __launch_bounds__(256, 1)
void gemm_h(const __half* __restrict__ A, int lda, long long strA,
            const __half* __restrict__ B, int ldb, long long strB,
            void* __restrict__ Cv, int ldc, long long strC, int K)
{
    const int m0 = blockIdx.y * 128;
    const int n0 = blockIdx.x * NT;
    if (MODE == 1 && n0 > m0) return;
    const int Keff = (MODE == 2) ? (m0 + 128) : K;
    A += (long long)blockIdx.z * strA;
    B += (long long)blockIdx.z * strB;

    extern __shared__ __half sh[];
    __half* sA = sh;                      // [3][128][72]
    __half* sB = sh + 3 * 128 * 72;       // [3][NT][72]

    const int tid = threadIdx.x;
    const int lane = tid & 31, wid = tid >> 5;
    const int wm = wid & 1, wn = wid >> 1;
    const int gid = lane >> 2, tig = lane & 3;
    constexpr int NN = NT / 32;

    float acc[4][NN][4];
#pragma unroll
    for (int mi = 0; mi < 4; mi++)
#pragma unroll
        for (int ni = 0; ni < NN; ni++)
#pragma unroll
            for (int j = 0; j < 4; j++) acc[mi][ni][j] = 0.f;

    auto load_chunk = [&](int ic, int p) {
        const __half* Ag = A + (long long)m0 * lda + ic * 64;
        uint32_t sAb = smem_u32(sA + p * 128 * 72);
#pragma unroll
        for (int it = 0; it < 4; it++) {
            int i = tid + it * 256;
            int r = i >> 3, seg = i & 7;
            cpa16(sAb + (r * 72 + seg * 8) * 2, Ag + (long long)r * lda + seg * 8);
        }
        const __half* Bg = B + (long long)n0 * ldb + ic * 64;
        uint32_t sBb = smem_u32(sB + p * NT * 72);
#pragma unroll
        for (int it = 0; it < NT / 32; it++) {
            int i = tid + it * 256;
            int r = i >> 3, seg = i & 7;
            cpa16(sBb + (r * 72 + seg * 8) * 2, Bg + (long long)r * ldb + seg * 8);
        }
        cp_commit();
    };

    const int aRow = wm * 64 + (lane & 15);
    const int aK   = (lane >> 4) << 3;
    const int bRow = wn * (NT / 4) + ((lane >> 4) << 3) + (lane & 7);
    const int bK   = ((lane >> 3) & 1) << 3;

    auto compute = [&](int p) {
        const uint32_t aBase = smem_u32(sA + p * 128 * 72) + (aRow * 72 + aK) * 2;
        const uint32_t bBase = smem_u32(sB + p * NT * 72) + (bRow * 72 + bK) * 2;
#pragma unroll
        for (int ks = 0; ks < 4; ks++) {
            const int k0 = ks * 16;
            uint32_t af[4][4], bf[NN][2];
#pragma unroll
            for (int mi = 0; mi < 4; mi++)
                ldmx4(af[mi], aBase + (mi * 16 * 72 + k0) * 2);
#pragma unroll
            for (int n2 = 0; n2 < NN / 2; n2++) {
                uint32_t t[4];
                ldmx4(t, bBase + (n2 * 16 * 72 + k0) * 2);
                bf[2 * n2][0] = t[0]; bf[2 * n2][1] = t[1];
                bf[2 * n2 + 1][0] = t[2]; bf[2 * n2 + 1][1] = t[3];
            }
#pragma unroll
            for (int mi = 0; mi < 4; mi++)
#pragma unroll
                for (int ni = 0; ni < NN; ni++)
                    mma16816(acc[mi][ni], af[mi], bf[ni]);
        }
    };

    const int nch = Keff >> 6;
    load_chunk(0, 0);
    if (nch > 1) load_chunk(1, 1);
    for (int ic = 0; ic < nch; ic++) {
        const int p = ic % 3;
        if (ic + 1 < nch)
            asm volatile("cp.async.wait_group 1;" ::: "memory");
        else
            asm volatile("cp.async.wait_group 0;" ::: "memory");
        __syncthreads();
        if (ic + 2 < nch) load_chunk(ic + 2, (ic + 2) % 3);
        compute(p);
    }

    // epilogue
#pragma unroll
    for (int mi = 0; mi < 4; mi++) {
        const int r0 = m0 + wm * 64 + mi * 16 + gid;
#pragma unroll
        for (int ni = 0; ni < NN; ni++) {
            const int c = n0 + wn * (NT / 4) + ni * 8 + tig * 2;
            if (HOUT) {
                __half* C = (__half*)Cv + (long long)blockIdx.z * strC;
                *(__half2*)(C + (long long)r0 * ldc + c) =
                    __floats2half2_rn(acc[mi][ni][0], acc[mi][ni][1]);
                *(__half2*)(C + (long long)(r0 + 8) * ldc + c) =
                    __floats2half2_rn(acc[mi][ni][2], acc[mi][ni][3]);
            } else {
                float* C = (float*)Cv + (long long)blockIdx.z * strC;
                *(float2*)(C + (long long)r0 * ldc + c) =
                    make_float2(acc[mi][ni][0], acc[mi][ni][1]);
                *(float2*)(C + (long long)(r0 + 8) * ldc + c) =
                    make_float2(acc[mi][ni][2], acc[mi][ni][3]);
            }
        }
    }
}

// ---------------- converters ------------------------------------------------------
__global__ void cvt_k(const float* __restrict__ in, __half* __restrict__ out, int n)
{
    int i = blockIdx.x * 256 + threadIdx.x;
    if (i < n) out[i] = __float2half_rn(in[i]);
}

// ---------------- RMSNorm (fp16 in/out, fp32 math) --------------------------------
__global__ __launch_bounds__(256)
void rmsnorm_k(const __half* __restrict__ in, int ldin, const float* __restrict__ w,
               __half* __restrict__ out, int ldout, int W)
{
    int row = blockIdx.x;
    const __half* x = in + (long long)row * ldin;
    float ss = 0.f;
    for (int i = threadIdx.x; i < W; i += 256) { float v = __half2float(x[i]); ss += v * v; }
#pragma unroll
    for (int o = 16; o > 0; o >>= 1) ss += __shfl_xor_sync(0xffffffffu, ss, o);
    __shared__ float red[8];
    if ((threadIdx.x & 31) == 0) red[threadIdx.x >> 5] = ss;
    __syncthreads();
    float tot = 0.f;
#pragma unroll
    for (int j = 0; j < 8; j++) tot += red[j];
    float sc = rsqrtf(tot / (float)W + 1e-6f);
    __half* o = out + (long long)row * ldout;
    for (int i = threadIdx.x; i < W; i += 256)
        o[i] = __float2half_rn(__half2float(x[i]) * sc * w[i]);
}

// ---------------- RoPE -------------------------------------------------------------
__global__ void rope_table_k(float* __restrict__ ctab, float* __restrict__ stab)
{
    int idx = blockIdx.x * blockDim.x + threadIdx.x;
    if (idx >= SEQ * 32) return;
    int s = idx >> 5, i = idx & 31;
    float invf = (float)pow(10000.0, -((double)i / 32.0));
    float f = (float)s * invf;
    double fd = (double)f;
    ctab[idx] = (float)cos(fd);
    stab[idx] = (float)sin(fd);
}
__global__ void rope_kpe_k(const __half* __restrict__ kva, __half* __restrict__ kcat,
                           const float* __restrict__ ctab, const float* __restrict__ stab)
{
    int idx = blockIdx.x * blockDim.x + threadIdx.x;
    if (idx >= SEQ * 32) return;
    int s = idx >> 5, i = idx & 31;
    float c = ctab[idx], sn = stab[idx];
    const __half* in = kva + (long long)s * DCAT + KVL;
    __half* out = kcat + (long long)s * DCAT + KVL;
    float x0 = __half2float(in[2 * i]), x1 = __half2float(in[2 * i + 1]);
    out[2 * i]     = __float2half_rn(x0 * c - x1 * sn);
    out[2 * i + 1] = __float2half_rn(x0 * sn + x1 * c);
}
// in-place RoPE on the q_pe slice of q [s][h*192 + 128 .. +191]
__global__ void rope_q_inplace_k(__half* __restrict__ q,
                                 const float* __restrict__ ctab, const float* __restrict__ stab)
{
    int idx = blockIdx.x * blockDim.x + threadIdx.x;
    if (idx >= NH * SEQ * 32) return;
    int i = idx & 31;
    int s = (idx >> 5) & (SEQ - 1);
    int h = idx >> 17;
    float c = ctab[(s << 5) + i], sn = stab[(s << 5) + i];
    __half* p = q + (long long)s * (NH * QKH) + h * QKH + NOPE;
    float x0 = __half2float(p[2 * i]), x1 = __half2float(p[2 * i + 1]);
    p[2 * i]     = __float2half_rn(x0 * c - x1 * sn);
    p[2 * i + 1] = __float2half_rn(x0 * sn + x1 * c);
}
// copy rope(k_pe) into khat cols 128..191 for every head
__global__ void copy_kpe_k(const __half* __restrict__ kcat, __half* __restrict__ khat)
{
    int idx = blockIdx.x * blockDim.x + threadIdx.x;
    if (idx >= NH * SEQ * 64) return;
    int j = idx & 63;
    int s = (idx >> 6) & (SEQ - 1);
    int h = idx >> 18;
    khat[((long long)h * SEQ + s) * QKH + NOPE + j] = kcat[(long long)s * DCAT + KVL + j];
}

// ---------------- causal softmax: fp32 scores -> fp16 probs ------------------------
__global__ __launch_bounds__(256)
void softmax_causal_k(const float* __restrict__ S, __half* __restrict__ P)
{
    int h = blockIdx.y;
    int s = blockIdx.x * 8 + (threadIdx.x >> 5);
    int lane = threadIdx.x & 31;
    const float* row = S + ((size_t)h * SEQ + s) * SEQ;
    __half* prow = P + ((size_t)h * SEQ + s) * SEQ;
    int n = s + 1;
    float m = -1e30f;
    for (int t = lane; t < n; t += 32) m = fmaxf(m, row[t]);
#pragma unroll
    for (int o = 16; o > 0; o >>= 1) m = fmaxf(m, __shfl_xor_sync(0xffffffffu, m, o));
    float l = 0.f;
    for (int t = lane; t < n; t += 32) l += expf((row[t] - m) * SCALE_F);
#pragma unroll
    for (int o = 16; o > 0; o >>= 1) l += __shfl_xor_sync(0xffffffffu, l, o);
    float inv = 1.f / l;
    for (int t = lane; t < n; t += 32)
        prow[t] = __float2half_rn(expf((row[t] - m) * SCALE_F) * inv);
    int bnd = ((s >> 7) + 1) << 7;   // zero-fill to 128-tile boundary
    for (int t = n + lane; t < bnd; t += 32) prow[t] = __float2half_rn(0.f);
}

// ---------------- launch ------------------------------------------------------------
extern "C" void kernel_launch(void* const* d_in, const int* in_sizes, int n_in,
                              void* d_out, int out_size)
{
    (void)in_sizes; (void)n_in; (void)out_size;
    const float* x       = (const float*)d_in[0];
    const float* wq_a    = (const float*)d_in[1];
    const float* q_norm  = (const float*)d_in[2];
    const float* wq_b    = (const float*)d_in[3];
    const float* wkv_a   = (const float*)d_in[4];
    const float* kv_norm = (const float*)d_in[5];
    const float* wkv_b   = (const float*)d_in[6];
    const float* wo      = (const float*)d_in[7];
    float* out = (float*)d_out;

    __half *xh, *wqa, *wqb, *wka, *wbr, *woh;
    __half *qa, *q, *kva, *kcat, *khat, *vT, *v, *P;
    float *ctab, *stab, *S;
    cudaGetSymbolAddress((void**)&xh,   g_xh);
    cudaGetSymbolAddress((void**)&wqa,  g_wqa);
    cudaGetSymbolAddress((void**)&wqb,  g_wqb);
    cudaGetSymbolAddress((void**)&wka,  g_wka);
    cudaGetSymbolAddress((void**)&wbr,  g_wbr);
    cudaGetSymbolAddress((void**)&woh,  g_woh);
    cudaGetSymbolAddress((void**)&qa,   g_qa);
    cudaGetSymbolAddress((void**)&q,    g_q);
    cudaGetSymbolAddress((void**)&kva,  g_kva);
    cudaGetSymbolAddress((void**)&kcat, g_kcat);
    cudaGetSymbolAddress((void**)&khat, g_khat);
    cudaGetSymbolAddress((void**)&vT,   g_vT);
    cudaGetSymbolAddress((void**)&v,    g_v);
    cudaGetSymbolAddress((void**)&ctab, g_cos);
    cudaGetSymbolAddress((void**)&stab, g_sin);
    cudaGetSymbolAddress((void**)&S,    g_S);
    cudaGetSymbolAddress((void**)&P,    g_P);

    cudaFuncSetAttribute(gemm_h<256,0,1>, cudaFuncAttributeMaxDynamicSharedMemorySize, SMEM_H(256));
    cudaFuncSetAttribute(gemm_h<256,0,0>, cudaFuncAttributeMaxDynamicSharedMemorySize, SMEM_H(256));
    cudaFuncSetAttribute(gemm_h<256,1,0>, cudaFuncAttributeMaxDynamicSharedMemorySize, SMEM_H(256));
    cudaFuncSetAttribute(gemm_h<128,0,1>, cudaFuncAttributeMaxDynamicSharedMemorySize, SMEM_H(128));
    cudaFuncSetAttribute(gemm_h<128,2,1>, cudaFuncAttributeMaxDynamicSharedMemorySize, SMEM_H(128));
    cudaFuncSetAttribute(gemm_h<64,0,1>,  cudaFuncAttributeMaxDynamicSharedMemorySize, SMEM_H(64));

    // ---- fp16 conversions of inputs ----
    cvt_k<<<(SEQ * DIM + 255) / 256, 256>>>(x, xh, SEQ * DIM);
    cvt_k<<<(QL * DIM + 255) / 256, 256>>>(wq_a, wqa, QL * DIM);
    cvt_k<<<(NH * QKH * QL + 255) / 256, 256>>>(wq_b, wqb, NH * QKH * QL);
    cvt_k<<<(DCAT * DIM + 255) / 256, 256>>>(wkv_a, wka, DCAT * DIM);
    cvt_k<<<(NH * 256 * KVL + 255) / 256, 256>>>(wkv_b, wbr, NH * 256 * KVL);
    cvt_k<<<(DIM * DIM + 255) / 256, 256>>>(wo, woh, DIM * DIM);
    rope_table_k<<<(SEQ * 32 + 255) / 256, 256>>>(ctab, stab);

    // qa = x @ wq_a^T ; rmsnorm ; q = qa @ wq_b^T ; rope q_pe in place
    gemm_h<256,0,1><<<dim3(QL / 256, 32, 1), 256, SMEM_H(256)>>>(
        xh, DIM, 0, wqa, DIM, 0, qa, QL, 0, DIM);
    rmsnorm_k<<<SEQ, 256>>>(qa, QL, q_norm, qa, QL, QL);
    gemm_h<256,0,1><<<dim3(NH * QKH / 256, 32, 1), 256, SMEM_H(256)>>>(
        qa, QL, 0, wqb, QL, 0, q, NH * QKH, 0, QL);
    rope_q_inplace_k<<<(NH * SEQ * 32) / 256, 256>>>(q, ctab, stab);

    // kva = x @ wkv_a^T ; kcat = [rmsnorm | rope]
    gemm_h<64,0,1><<<dim3(DCAT / 64, 32, 1), 256, SMEM_H(64)>>>(
        xh, DIM, 0, wka, DIM, 0, kva, DCAT, 0, DIM);
    rmsnorm_k<<<SEQ, 256>>>(kva, DCAT, kv_norm, kcat, DCAT, KVL);
    rope_kpe_k<<<(SEQ * 32 + 255) / 256, 256>>>(kva, kcat, ctab, stab);

    // khat[h][:, :128] = kv @ wkv_b[h, :128, :]^T ; cols 128..191 = k_pe
    gemm_h<128,0,1><<<dim3(1, 32, NH), 256, SMEM_H(128)>>>(
        kcat, DCAT, 0,
        wbr, KVL, (long long)256 * KVL,
        khat, QKH, (long long)SEQ * QKH, KVL);
    copy_kpe_k<<<(NH * SEQ * 64) / 256, 256>>>(kcat, khat);

    // vT[h] = wkv_b[h, 128:, :] @ kv^T  -> [128, SEQ] per head
    gemm_h<256,0,1><<<dim3(SEQ / 256, 1, NH), 256, SMEM_H(256)>>>(
        wbr + (long long)NOPE * KVL, KVL, (long long)256 * KVL,
        kcat, DCAT, 0,
        vT, SEQ, (long long)NOPE * SEQ, KVL);

    // scores: S[h] = q_h @ khat_h^T  (K=192, causal tiles, fp32 out)
    gemm_h<256,1,0><<<dim3(SEQ / 256, 32, NH), 256, SMEM_H(256)>>>(
        q, NH * QKH, QKH,
        khat, QKH, (long long)SEQ * QKH,
        S, SEQ, (long long)SEQ * SEQ, QKH);

    softmax_causal_k<<<dim3(SEQ / 8, NH), 256>>>(S, P);

    // v[:, h*128..] = P[h] @ vT[h]^T  (K truncated to m0+128)
    gemm_h<128,2,1><<<dim3(1, 32, NH), 256, SMEM_H(128)>>>(
        P, SEQ, (long long)SEQ * SEQ,
        vT, SEQ, (long long)NOPE * SEQ,
        v, DIM, NOPE, SEQ);

    // out = v @ wo^T (fp32 out)
    gemm_h<256,0,0><<<dim3(DIM / 256, 32, 1), 256, SMEM_H(256)>>>(
        v, DIM, 0, woh, DIM, 0, out, DIM, 0, DIM);
}